// round 5
// baseline (speedup 1.0000x reference)
#include <cuda_runtime.h>

// ---------------- problem constants ----------------
#define BSZ   4
#define NN    512
#define EMBD  64
#define INF   256          // IN_DIM
#define H1    128          // fc1 out (2*HD)
#define HE    64           // e1 out
#define NPAIR (NN*(NN-1))                 // 261632
#define PRED_OFF (BSZ*NN*NN)              // 1048576
#define EMB_OFF  (PRED_OFF + BSZ*NPAIR*2) // 3141632

// ---------------- device scratch (no allocs allowed) ----------------
__device__ float g_emb[BSZ*NN*EMBD];     // emb row-major [b][n][k]
__device__ float g_A  [BSZ*NN*HE];       // emb @ W1top   [b][n][h]

typedef unsigned int u32;

// =====================================================================
// Stage 1: node MLP (unchanged).
// =====================================================================
__global__ __launch_bounds__(256)
void stage1(const float* __restrict__ nf,
            const float* __restrict__ fc1w, const float* __restrict__ fc1b,
            const float* __restrict__ fc2w, const float* __restrict__ fc2b,
            const float* __restrict__ e1w,
            float* __restrict__ out)
{
    extern __shared__ float sm[];
    float* Xs = sm;             // 16*256 = 4096 floats
    float* Ws = Xs + 4096;      // up to 8192 floats
    float* Hs = Ws + 8192;      // 16*132 = 2112
    float* Es = Hs + 2112;      // 16*64  = 1024

    const int t  = threadIdx.x;
    const int nb = blockIdx.x * 16;
    const int node = t >> 4;
    const int sub  = t & 15;

    #pragma unroll
    for (int r = 0; r < 16; r++)
        Xs[t + r*256] = nf[nb*INF + t + r*256];

    {   // phase A: h = leaky(x@fc1+b1)
        const int hb = sub * 8;
        float acc[8];
        #pragma unroll
        for (int h = 0; h < 8; h++) acc[h] = 0.f;
        for (int kt = 0; kt < 4; kt++) {
            __syncthreads();
            #pragma unroll
            for (int r = 0; r < 32; r++)
                Ws[t + r*256] = fc1w[kt*64*H1 + t + r*256];
            __syncthreads();
            #pragma unroll
            for (int k = 0; k < 64; k++) {
                float x = Xs[node*INF + kt*64 + k];
                float4 w0 = *reinterpret_cast<const float4*>(&Ws[k*H1 + hb]);
                float4 w1 = *reinterpret_cast<const float4*>(&Ws[k*H1 + hb + 4]);
                acc[0] += x*w0.x; acc[1] += x*w0.y; acc[2] += x*w0.z; acc[3] += x*w0.w;
                acc[4] += x*w1.x; acc[5] += x*w1.y; acc[6] += x*w1.z; acc[7] += x*w1.w;
            }
        }
        #pragma unroll
        for (int h = 0; h < 8; h++) {
            float v = acc[h] + fc1b[hb + h];
            v = v > 0.f ? v : 0.01f * v;
            Hs[node*132 + hb + h] = v;
        }
    }

    __syncthreads();
    #pragma unroll
    for (int r = 0; r < 32; r++)
        Ws[t + r*256] = fc2w[t + r*256];
    __syncthreads();
    {   // phase B: emb = leaky(h@fc2+b2)
        const int db = sub * 4;
        float a0=0.f,a1=0.f,a2=0.f,a3=0.f;
        #pragma unroll
        for (int k = 0; k < H1; k++) {
            float hv = Hs[node*132 + k];
            float4 w = *reinterpret_cast<const float4*>(&Ws[k*EMBD + db]);
            a0 += hv*w.x; a1 += hv*w.y; a2 += hv*w.z; a3 += hv*w.w;
        }
        float v0 = a0 + fc2b[db+0]; v0 = v0 > 0.f ? v0 : 0.01f*v0;
        float v1 = a1 + fc2b[db+1]; v1 = v1 > 0.f ? v1 : 0.01f*v1;
        float v2 = a2 + fc2b[db+2]; v2 = v2 > 0.f ? v2 : 0.01f*v2;
        float v3 = a3 + fc2b[db+3]; v3 = v3 > 0.f ? v3 : 0.01f*v3;

        Es[node*EMBD + db + 0] = v0;
        Es[node*EMBD + db + 1] = v1;
        Es[node*EMBD + db + 2] = v2;
        Es[node*EMBD + db + 3] = v3;

        const int g = nb + node;
        float4 v4 = make_float4(v0, v1, v2, v3);
        *reinterpret_cast<float4*>(&g_emb[g*EMBD + db]) = v4;
        *reinterpret_cast<float4*>(&out[EMB_OFF + g*EMBD + db]) = v4;
    }

    __syncthreads();
    #pragma unroll
    for (int r = 0; r < 16; r++)
        Ws[t + r*256] = e1w[t + r*256];
    __syncthreads();
    {   // phase C: A = emb @ e1_w[:64,:]
        const int hb = sub * 4;
        float a0=0.f,a1=0.f,a2=0.f,a3=0.f;
        #pragma unroll
        for (int k = 0; k < EMBD; k++) {
            float ev = Es[node*EMBD + k];
            float4 w = *reinterpret_cast<const float4*>(&Ws[k*HE + hb]);
            a0 += ev*w.x; a1 += ev*w.y; a2 += ev*w.z; a3 += ev*w.w;
        }
        const int g = nb + node;
        *reinterpret_cast<float4*>(&g_A[g*HE + hb]) = make_float4(a0, a1, a2, a3);
    }
}

// =====================================================================
// Stage 2: edge GEMM via mma.sync (HMMA bf16, compensated split).
// j-tile 256, 2 CTAs/SM, W read from global (L1/L2-resident).
// =====================================================================
// smem byte offsets
#define EHB   0          // Eh: 256 x 64 bf16, 128B rows, SW128   = 32768
#define ELB   32768      // El: same                               = 32768
#define UHB   65536      // Uh: 64 x 64 bf16                       = 8192
#define ULB   73728      // Ul                                     = 8192
#define EMBA  81920      // emb_i 16 x 64 f32                      = 4096
#define CCB   86016      // cc 16 x 64 f32                         = 4096
#define WDB   90112      // wd 64 f32                              = 256
#define SM2_TOTAL 90368

__device__ __forceinline__ u32 bfpack(float lo, float hi) {
    u32 r;
    asm("cvt.rn.satfinite.bf16x2.f32 %0, %1, %2;" : "=r"(r) : "f"(hi), "f"(lo));
    return r;
}
__device__ __forceinline__ float bf_lo_f(u32 p) { return __uint_as_float(p << 16); }
__device__ __forceinline__ float bf_hi_f(u32 p) { return __uint_as_float(p & 0xFFFF0000u); }

__device__ __forceinline__ void ldsm4(u32& r0, u32& r1, u32& r2, u32& r3, u32 addr) {
    asm volatile("ldmatrix.sync.aligned.m8n8.x4.shared.b16 {%0,%1,%2,%3}, [%4];"
        : "=r"(r0), "=r"(r1), "=r"(r2), "=r"(r3) : "r"(addr));
}
__device__ __forceinline__ void ldsm4t(u32& r0, u32& r1, u32& r2, u32& r3, u32 addr) {
    asm volatile("ldmatrix.sync.aligned.m8n8.x4.trans.shared.b16 {%0,%1,%2,%3}, [%4];"
        : "=r"(r0), "=r"(r1), "=r"(r2), "=r"(r3) : "r"(addr));
}
__device__ __forceinline__ void mma16816(float* d, const u32* a, const u32* b) {
    asm volatile(
        "mma.sync.aligned.m16n8k16.row.col.f32.bf16.bf16.f32 "
        "{%0,%1,%2,%3}, {%4,%5,%6,%7}, {%8,%9}, {%0,%1,%2,%3};"
        : "+f"(d[0]), "+f"(d[1]), "+f"(d[2]), "+f"(d[3])
        : "r"(a[0]), "r"(a[1]), "r"(a[2]), "r"(a[3]), "r"(b[0]), "r"(b[1]));
}

__device__ __forceinline__ void store_edge(float* __restrict__ out,
                                           int b, int i, int j, float d) {
    float ad  = fabsf(d);
    float ex  = __expf(-ad);
    float inv = 1.f / (1.f + ex);
    float pbig = inv, psml = ex * inv;
    float p1 = d >= 0.f ? pbig : psml;
    float p0 = d >= 0.f ? psml : pbig;
    out[b*NN*NN + i*NN + j] = p1;
    if (j != i) {
        int kidx = i*(NN-1) + (j < i ? j : j - 1);
        reinterpret_cast<float2*>(out + PRED_OFF)[b*NPAIR + kidx] = make_float2(p0, p1);
    }
}

__global__ __launch_bounds__(256, 2)
void stage2m(const float* __restrict__ e1w, const float* __restrict__ e1b,
             const float* __restrict__ e2w, const float* __restrict__ e2b,
             float* __restrict__ out)
{
    extern __shared__ char smc[];
    const u32 sb = (u32)__cvta_generic_to_shared(smc);

    const int t    = threadIdx.x;
    const int lane = t & 31;
    const int wid  = t >> 5;

    const int bid = blockIdx.x;
    const int b   = bid >> 6;
    const int ig  = (bid & 63) >> 1;
    const int jt  = bid & 1;
    const int ibase = ig * 16;
    const int jb    = jt * 256;

    float* embA = reinterpret_cast<float*>(smc + EMBA);
    float* ccs  = reinterpret_cast<float*>(smc + CCB);
    float* wds  = reinterpret_cast<float*>(smc + WDB);

    // ---- prologue: emb_i, cc, wd ----
    reinterpret_cast<float4*>(embA)[t] =
        reinterpret_cast<const float4*>(&g_emb[(b*NN + ibase)*EMBD])[t];
    #pragma unroll
    for (int r = 0; r < 4; r++) {
        int idx = t + r*256, ii = idx >> 6, h = idx & 63;
        ccs[idx] = g_A[(b*NN + ibase + ii)*HE + h] + e1b[h];
    }
    if (t < 64) wds[t] = e2w[t*2 + 1] - e2w[t*2];
    const float bd = e2b[1] - e2b[0];

    // ---- E conversion: row t (of 256) -> Eh/El (SW128 swizzled) ----
    {
        const int r = t;
        const float4* src = reinterpret_cast<const float4*>(&g_emb[(b*NN + jb + r)*EMBD]);
        char* ehrow = smc + EHB + r*128;
        char* elrow = smc + ELB + r*128;
        const int r7 = r & 7;
        #pragma unroll
        for (int c = 0; c < 8; c++) {
            float4 v0 = src[c*2], v1 = src[c*2 + 1];
            u32 h0 = bfpack(v0.x, v0.y), h1 = bfpack(v0.z, v0.w);
            u32 h2 = bfpack(v1.x, v1.y), h3 = bfpack(v1.z, v1.w);
            u32 l0 = bfpack(v0.x - bf_lo_f(h0), v0.y - bf_hi_f(h0));
            u32 l1 = bfpack(v0.z - bf_lo_f(h1), v0.w - bf_hi_f(h1));
            u32 l2 = bfpack(v1.x - bf_lo_f(h2), v1.y - bf_hi_f(h2));
            u32 l3 = bfpack(v1.z - bf_lo_f(h3), v1.w - bf_hi_f(h3));
            *reinterpret_cast<uint4*>(ehrow + ((c ^ r7) << 4)) = make_uint4(h0, h1, h2, h3);
            *reinterpret_cast<uint4*>(elrow + ((c ^ r7) << 4)) = make_uint4(l0, l1, l2, l3);
        }
    }
    __syncthreads();

    const u32 EhA = sb + EHB, ElA = sb + ELB, UhA = sb + UHB, UlA = sb + ULB;
    const int wj   = wid * 32;
    const int lrow = lane & 15;
    const int lch  = lane >> 4;      // 0/1: chunk selector

    // ---- loop over 16 source nodes ----
    for (int ii = 0; ii < 16; ii++) {
        // build Uh/Ul (all 256 threads; k = t>>2, 2 col-chunks each). W from global.
        {
            const int k  = t >> 2;
            const int c2 = (t & 3) * 2;
            const float e = embA[ii*64 + k];
            const float4* w1 = reinterpret_cast<const float4*>(&e1w[k*64 + c2*8]);
            const float4* w2 = reinterpret_cast<const float4*>(&e1w[4096 + k*64 + c2*8]);
            char* uh = smc + UHB + k*128;
            char* ul = smc + ULB + k*128;
            const int k7 = k & 7;
            #pragma unroll
            for (int q = 0; q < 2; q++) {
                float4 a0 = w1[q*2], a1 = w1[q*2 + 1];
                float4 b0 = w2[q*2], b1 = w2[q*2 + 1];
                float u0 = fmaf(e, b0.x, -a0.x), u1 = fmaf(e, b0.y, -a0.y);
                float u2 = fmaf(e, b0.z, -a0.z), u3 = fmaf(e, b0.w, -a0.w);
                float u4 = fmaf(e, b1.x, -a1.x), u5 = fmaf(e, b1.y, -a1.y);
                float u6 = fmaf(e, b1.z, -a1.z), u7 = fmaf(e, b1.w, -a1.w);
                u32 p0 = bfpack(u0, u1), p1 = bfpack(u2, u3);
                u32 p2 = bfpack(u4, u5), p3 = bfpack(u6, u7);
                u32 q0 = bfpack(u0 - bf_lo_f(p0), u1 - bf_hi_f(p0));
                u32 q1 = bfpack(u2 - bf_lo_f(p1), u3 - bf_hi_f(p1));
                u32 q2 = bfpack(u4 - bf_lo_f(p2), u5 - bf_hi_f(p2));
                u32 q3 = bfpack(u6 - bf_lo_f(p3), u7 - bf_hi_f(p3));
                const u32 co = (u32)(((c2 + q) ^ k7) << 4);
                *reinterpret_cast<uint4*>(uh + co) = make_uint4(p0, p1, p2, p3);
                *reinterpret_cast<uint4*>(ul + co) = make_uint4(q0, q1, q2, q3);
            }
        }
        __syncthreads();

        // mma: warp tile 32j x 64h, 3 compensation passes
        float acc[16][4];
        #pragma unroll
        for (int a = 0; a < 16; a++)
            #pragma unroll
            for (int c = 0; c < 4; c++) acc[a][c] = 0.f;

        #pragma unroll
        for (int p = 0; p < 3; p++) {
            const u32 Eb = (p == 2) ? ElA : EhA;
            const u32 Ub = (p == 1) ? UlA : UhA;
            #pragma unroll
            for (int ks = 0; ks < 4; ks++) {
                const int k0 = ks * 16;
                // B frags: 4 x ldmatrix.x4.trans covering k0..k0+15 x 64h
                u32 bfr[8][2];
                const int  kr  = k0 + lrow;
                const u32  brb = Ub + (u32)(kr * 128);
                const int  br7 = kr & 7;
                #pragma unroll
                for (int nb = 0; nb < 4; nb++) {
                    const u32 addr = brb + (u32)((((nb*2 + lch) ^ br7)) << 4);
                    ldsm4t(bfr[nb*2][0], bfr[nb*2][1],
                           bfr[nb*2+1][0], bfr[nb*2+1][1], addr);
                }
                #pragma unroll
                for (int jf = 0; jf < 2; jf++) {
                    const int ra = wj + jf*16 + lrow;
                    const u32 addr = Eb + (u32)(ra*128)
                                   + (u32)((((ks*2 + lch) ^ (ra & 7))) << 4);
                    u32 a[4];
                    ldsm4(a[0], a[1], a[2], a[3], addr);
                    #pragma unroll
                    for (int ht = 0; ht < 8; ht++)
                        mma16816(acc[jf*8 + ht], a, bfr[ht]);
                }
            }
        }

        // epilogue: relu + wd dot, bfly-reduce over lane%4, sigmoid, store
        {
            const int t2 = (lane & 3) * 2;
            const int ig2 = ibase + ii;
            #pragma unroll
            for (int jf = 0; jf < 2; jf++) {
                float s0 = 0.f, s1 = 0.f;
                #pragma unroll
                for (int ht = 0; ht < 8; ht++) {
                    float cc0 = ccs[ii*64 + ht*8 + t2];
                    float cc1 = ccs[ii*64 + ht*8 + t2 + 1];
                    float wd0 = wds[ht*8 + t2];
                    float wd1 = wds[ht*8 + t2 + 1];
                    s0 += fmaxf(acc[jf*8+ht][0] + cc0, 0.f) * wd0
                        + fmaxf(acc[jf*8+ht][1] + cc1, 0.f) * wd1;
                    s1 += fmaxf(acc[jf*8+ht][2] + cc0, 0.f) * wd0
                        + fmaxf(acc[jf*8+ht][3] + cc1, 0.f) * wd1;
                }
                s0 += __shfl_xor_sync(0xffffffffu, s0, 1);
                s0 += __shfl_xor_sync(0xffffffffu, s0, 2);
                s1 += __shfl_xor_sync(0xffffffffu, s1, 1);
                s1 += __shfl_xor_sync(0xffffffffu, s1, 2);
                if ((lane & 3) == 0) {
                    const int j0 = jb + wj + jf*16 + (lane >> 2);
                    store_edge(out, b, ig2, j0,     s0 + bd);
                    store_edge(out, b, ig2, j0 + 8, s1 + bd);
                }
            }
        }
        __syncthreads();
    }
}

// =====================================================================
extern "C" void kernel_launch(void* const* d_in, const int* in_sizes, int n_in,
                              void* d_out, int out_size)
{
    (void)in_sizes; (void)n_in; (void)out_size;
    const float* nf   = (const float*)d_in[0];
    const float* fc1w = (const float*)d_in[1];
    const float* fc1b = (const float*)d_in[2];
    const float* fc2w = (const float*)d_in[3];
    const float* fc2b = (const float*)d_in[4];
    const float* e1w  = (const float*)d_in[5];
    const float* e1b  = (const float*)d_in[6];
    const float* e2w  = (const float*)d_in[7];
    const float* e2b  = (const float*)d_in[8];
    float* out = (float*)d_out;

    const int smem1 = 15424 * 4;
    cudaFuncSetAttribute(stage1, cudaFuncAttributeMaxDynamicSharedMemorySize, smem1);
    cudaFuncSetAttribute(stage2m, cudaFuncAttributeMaxDynamicSharedMemorySize, SM2_TOTAL);

    stage1<<<128, 256, smem1>>>(nf, fc1w, fc1b, fc2w, fc2b, e1w, out);
    stage2m<<<256, 256, SM2_TOTAL>>>(e1w, e1b, e2w, e2b, out);
}

// round 6
// speedup vs baseline: 1.4287x; 1.4287x over previous
#include <cuda_runtime.h>
#include <cuda_fp16.h>

// ---------------- problem constants ----------------
#define BSZ   4
#define NN    512
#define EMBD  64
#define INF   256          // IN_DIM
#define H1    128          // fc1 out (2*HD)
#define HE    64           // e1 out
#define NPAIR (NN*(NN-1))                 // 261632
#define PRED_OFF (BSZ*NN*NN)              // 1048576
#define EMB_OFF  (PRED_OFF + BSZ*NPAIR*2) // 3141632

// ---------------- device scratch (no allocs allowed) ----------------
__device__ float g_emb[BSZ*NN*EMBD];     // emb row-major [b][n][k]
__device__ float g_A  [BSZ*NN*HE];       // emb @ W1top   [b][n][h]

typedef unsigned int u32;

// =====================================================================
// Stage 1: node MLP (unchanged).
// =====================================================================
__global__ __launch_bounds__(256)
void stage1(const float* __restrict__ nf,
            const float* __restrict__ fc1w, const float* __restrict__ fc1b,
            const float* __restrict__ fc2w, const float* __restrict__ fc2b,
            const float* __restrict__ e1w,
            float* __restrict__ out)
{
    extern __shared__ float sm[];
    float* Xs = sm;             // 16*256 = 4096 floats
    float* Ws = Xs + 4096;      // up to 8192 floats
    float* Hs = Ws + 8192;      // 16*132 = 2112
    float* Es = Hs + 2112;      // 16*64  = 1024

    const int t  = threadIdx.x;
    const int nb = blockIdx.x * 16;
    const int node = t >> 4;
    const int sub  = t & 15;

    #pragma unroll
    for (int r = 0; r < 16; r++)
        Xs[t + r*256] = nf[nb*INF + t + r*256];

    {   // phase A: h = leaky(x@fc1+b1)
        const int hb = sub * 8;
        float acc[8];
        #pragma unroll
        for (int h = 0; h < 8; h++) acc[h] = 0.f;
        for (int kt = 0; kt < 4; kt++) {
            __syncthreads();
            #pragma unroll
            for (int r = 0; r < 32; r++)
                Ws[t + r*256] = fc1w[kt*64*H1 + t + r*256];
            __syncthreads();
            #pragma unroll
            for (int k = 0; k < 64; k++) {
                float x = Xs[node*INF + kt*64 + k];
                float4 w0 = *reinterpret_cast<const float4*>(&Ws[k*H1 + hb]);
                float4 w1 = *reinterpret_cast<const float4*>(&Ws[k*H1 + hb + 4]);
                acc[0] += x*w0.x; acc[1] += x*w0.y; acc[2] += x*w0.z; acc[3] += x*w0.w;
                acc[4] += x*w1.x; acc[5] += x*w1.y; acc[6] += x*w1.z; acc[7] += x*w1.w;
            }
        }
        #pragma unroll
        for (int h = 0; h < 8; h++) {
            float v = acc[h] + fc1b[hb + h];
            v = v > 0.f ? v : 0.01f * v;
            Hs[node*132 + hb + h] = v;
        }
    }

    __syncthreads();
    #pragma unroll
    for (int r = 0; r < 32; r++)
        Ws[t + r*256] = fc2w[t + r*256];
    __syncthreads();
    {   // phase B: emb = leaky(h@fc2+b2)
        const int db = sub * 4;
        float a0=0.f,a1=0.f,a2=0.f,a3=0.f;
        #pragma unroll
        for (int k = 0; k < H1; k++) {
            float hv = Hs[node*132 + k];
            float4 w = *reinterpret_cast<const float4*>(&Ws[k*EMBD + db]);
            a0 += hv*w.x; a1 += hv*w.y; a2 += hv*w.z; a3 += hv*w.w;
        }
        float v0 = a0 + fc2b[db+0]; v0 = v0 > 0.f ? v0 : 0.01f*v0;
        float v1 = a1 + fc2b[db+1]; v1 = v1 > 0.f ? v1 : 0.01f*v1;
        float v2 = a2 + fc2b[db+2]; v2 = v2 > 0.f ? v2 : 0.01f*v2;
        float v3 = a3 + fc2b[db+3]; v3 = v3 > 0.f ? v3 : 0.01f*v3;

        Es[node*EMBD + db + 0] = v0;
        Es[node*EMBD + db + 1] = v1;
        Es[node*EMBD + db + 2] = v2;
        Es[node*EMBD + db + 3] = v3;

        const int g = nb + node;
        float4 v4 = make_float4(v0, v1, v2, v3);
        *reinterpret_cast<float4*>(&g_emb[g*EMBD + db]) = v4;
        *reinterpret_cast<float4*>(&out[EMB_OFF + g*EMBD + db]) = v4;
    }

    __syncthreads();
    #pragma unroll
    for (int r = 0; r < 16; r++)
        Ws[t + r*256] = e1w[t + r*256];
    __syncthreads();
    {   // phase C: A = emb @ e1_w[:64,:]
        const int hb = sub * 4;
        float a0=0.f,a1=0.f,a2=0.f,a3=0.f;
        #pragma unroll
        for (int k = 0; k < EMBD; k++) {
            float ev = Es[node*EMBD + k];
            float4 w = *reinterpret_cast<const float4*>(&Ws[k*HE + hb]);
            a0 += ev*w.x; a1 += ev*w.y; a2 += ev*w.z; a3 += ev*w.w;
        }
        const int g = nb + node;
        *reinterpret_cast<float4*>(&g_A[g*HE + hb]) = make_float4(a0, a1, a2, a3);
    }
}

// =====================================================================
// Stage 2: edge GEMM via mma.sync fp16, E split (Eh+El), U single-precision
// fp16, double-buffered. Grid 128, 1 CTA/SM, warp tile 64j x 64h.
// =====================================================================
// smem byte offsets
#define EHB   0          // Eh: 512 x 64 fp16, 128B rows, SW128   = 65536
#define ELB   65536      // El: same                               = 65536
#define UB0   131072     // Uh buf0: 64 x 64 fp16                  = 8192
#define UB1   139264     // Uh buf1                                = 8192
#define WB    147456     // e1w fp32 (8192 floats)                 = 32768
#define EMBA  180224     // emb_i 16 x 64 f32                      = 4096
#define CCB   184320     // cc 16 x 64 f32                         = 4096
#define WDB   188416     // wd 64 f32                              = 256
#define SM2_TOTAL 188672

__device__ __forceinline__ u32 hpack(float lo, float hi) {
    __half2 h = __floats2half2_rn(lo, hi);
    return *reinterpret_cast<u32*>(&h);
}
__device__ __forceinline__ float h_lo(u32 p) {
    __half2 h = *reinterpret_cast<__half2*>(&p);
    return __low2float(h);
}
__device__ __forceinline__ float h_hi(u32 p) {
    __half2 h = *reinterpret_cast<__half2*>(&p);
    return __high2float(h);
}

__device__ __forceinline__ void ldsm4(u32& r0, u32& r1, u32& r2, u32& r3, u32 addr) {
    asm volatile("ldmatrix.sync.aligned.m8n8.x4.shared.b16 {%0,%1,%2,%3}, [%4];"
        : "=r"(r0), "=r"(r1), "=r"(r2), "=r"(r3) : "r"(addr));
}
__device__ __forceinline__ void ldsm4t(u32& r0, u32& r1, u32& r2, u32& r3, u32 addr) {
    asm volatile("ldmatrix.sync.aligned.m8n8.x4.trans.shared.b16 {%0,%1,%2,%3}, [%4];"
        : "=r"(r0), "=r"(r1), "=r"(r2), "=r"(r3) : "r"(addr));
}
__device__ __forceinline__ void mma16816(float* d, const u32* a, const u32* b) {
    asm volatile(
        "mma.sync.aligned.m16n8k16.row.col.f32.f16.f16.f32 "
        "{%0,%1,%2,%3}, {%4,%5,%6,%7}, {%8,%9}, {%0,%1,%2,%3};"
        : "+f"(d[0]), "+f"(d[1]), "+f"(d[2]), "+f"(d[3])
        : "r"(a[0]), "r"(a[1]), "r"(a[2]), "r"(a[3]), "r"(b[0]), "r"(b[1]));
}

__device__ __forceinline__ void store_edge(float* __restrict__ out,
                                           int b, int i, int j, float d) {
    float ad  = fabsf(d);
    float ex  = __expf(-ad);
    float inv = 1.f / (1.f + ex);
    float pbig = inv, psml = ex * inv;
    float p1 = d >= 0.f ? pbig : psml;
    float p0 = d >= 0.f ? psml : pbig;
    out[b*NN*NN + i*NN + j] = p1;
    if (j != i) {
        int kidx = i*(NN-1) + (j < i ? j : j - 1);
        reinterpret_cast<float2*>(out + PRED_OFF)[b*NPAIR + kidx] = make_float2(p0, p1);
    }
}

__global__ __launch_bounds__(256, 1)
void stage2m(const float* __restrict__ e1w, const float* __restrict__ e1b,
             const float* __restrict__ e2w, const float* __restrict__ e2b,
             float* __restrict__ out)
{
    extern __shared__ char smc[];
    const u32 sb = (u32)__cvta_generic_to_shared(smc);

    const int t    = threadIdx.x;
    const int lane = t & 31;
    const int wid  = t >> 5;
    const int b     = blockIdx.x >> 5;
    const int ibase = (blockIdx.x & 31) * 16;

    float* Wsm  = reinterpret_cast<float*>(smc + WB);
    float* embA = reinterpret_cast<float*>(smc + EMBA);
    float* ccs  = reinterpret_cast<float*>(smc + CCB);
    float* wds  = reinterpret_cast<float*>(smc + WDB);

    // ---- prologue: weights, emb_i, cc, wd ----
    #pragma unroll
    for (int r = 0; r < 8; r++)
        reinterpret_cast<float4*>(Wsm)[t + r*256] =
            reinterpret_cast<const float4*>(e1w)[t + r*256];
    reinterpret_cast<float4*>(embA)[t] =
        reinterpret_cast<const float4*>(&g_emb[(b*NN + ibase)*EMBD])[t];
    #pragma unroll
    for (int r = 0; r < 4; r++) {
        int idx = t + r*256, ii = idx >> 6, h = idx & 63;
        ccs[idx] = g_A[(b*NN + ibase + ii)*HE + h] + e1b[h];
    }
    if (t < 64) wds[t] = e2w[t*2 + 1] - e2w[t*2];
    const float bd = e2b[1] - e2b[0];

    // ---- E conversion: rows t, t+256 -> Eh/El fp16 (SW128 swizzled) ----
    #pragma unroll
    for (int rr = 0; rr < 2; rr++) {
        const int r = t + rr*256;
        const float4* src = reinterpret_cast<const float4*>(&g_emb[(b*NN + r)*EMBD]);
        char* ehrow = smc + EHB + r*128;
        char* elrow = smc + ELB + r*128;
        const int r7 = r & 7;
        #pragma unroll
        for (int c = 0; c < 8; c++) {
            float4 v0 = src[c*2], v1 = src[c*2 + 1];
            u32 h0 = hpack(v0.x, v0.y), h1 = hpack(v0.z, v0.w);
            u32 h2 = hpack(v1.x, v1.y), h3 = hpack(v1.z, v1.w);
            u32 l0 = hpack(v0.x - h_lo(h0), v0.y - h_hi(h0));
            u32 l1 = hpack(v0.z - h_lo(h1), v0.w - h_hi(h1));
            u32 l2 = hpack(v1.x - h_lo(h2), v1.y - h_hi(h2));
            u32 l3 = hpack(v1.z - h_lo(h3), v1.w - h_hi(h3));
            *reinterpret_cast<uint4*>(ehrow + ((c ^ r7) << 4)) = make_uint4(h0, h1, h2, h3);
            *reinterpret_cast<uint4*>(elrow + ((c ^ r7) << 4)) = make_uint4(l0, l1, l2, l3);
        }
    }

    // ---- build U[0] into buf0 (before first sync) ----
    {
        const int k  = t >> 2;
        const int c2 = (t & 3) * 2;
        const float e = embA[0*64 + k];   // note: embA written this block pre-sync
        // embA was written by this thread block before; but need barrier? embA
        // written above by all threads; must sync before reading others' rows.
        // -> moved below; see after __syncthreads().
        (void)k; (void)c2; (void)e;
    }
    __syncthreads();

    // wd into registers: thread's h-cols are ht*8 + 2*(lane&3) + {0,1}
    float wdr[16];
    {
        const int t2 = (lane & 3) * 2;
        #pragma unroll
        for (int ht = 0; ht < 8; ht++) {
            wdr[ht*2]     = wds[ht*8 + t2];
            wdr[ht*2 + 1] = wds[ht*8 + t2 + 1];
        }
    }

    const u32 EhA = sb + EHB, ElA = sb + ELB;
    const int wj   = wid * 64;
    const int lrow = lane & 15;
    const int lch  = lane >> 4;      // 0/1: chunk selector

    // U build helper (inlined lambda): build Uh for source ii into buffer ub
    auto build_u = [&](int ii, u32 ubOff) {
        const int k  = t >> 2;
        const int c2 = (t & 3) * 2;
        const float e = embA[ii*64 + k];
        const float4* w1 = reinterpret_cast<const float4*>(&Wsm[k*64 + c2*8]);
        const float4* w2 = reinterpret_cast<const float4*>(&Wsm[4096 + k*64 + c2*8]);
        char* uh = smc + ubOff + k*128;
        const int k7 = k & 7;
        #pragma unroll
        for (int q = 0; q < 2; q++) {
            float4 a0 = w1[q*2], a1 = w1[q*2 + 1];
            float4 b0 = w2[q*2], b1 = w2[q*2 + 1];
            float u0 = fmaf(e, b0.x, -a0.x), u1 = fmaf(e, b0.y, -a0.y);
            float u2 = fmaf(e, b0.z, -a0.z), u3 = fmaf(e, b0.w, -a0.w);
            float u4 = fmaf(e, b1.x, -a1.x), u5 = fmaf(e, b1.y, -a1.y);
            float u6 = fmaf(e, b1.z, -a1.z), u7 = fmaf(e, b1.w, -a1.w);
            u32 p0 = hpack(u0, u1), p1 = hpack(u2, u3);
            u32 p2 = hpack(u4, u5), p3 = hpack(u6, u7);
            const u32 co = (u32)(((c2 + q) ^ k7) << 4);
            *reinterpret_cast<uint4*>(uh + co) = make_uint4(p0, p1, p2, p3);
        }
    };

    // build U[0], then sync so all warps see it
    build_u(0, UB0);
    __syncthreads();

    // ---- loop over 16 source nodes, U double-buffered ----
    for (int ii = 0; ii < 16; ii++) {
        // build U[ii+1] into the other buffer (no barrier needed before mma:
        // different buffer; previous readers of that buffer finished at the
        // end-of-iteration barrier of (ii-1)).
        if (ii + 1 < 16)
            build_u(ii + 1, ((ii + 1) & 1) ? UB1 : UB0);

        const u32 Ub = sb + ((ii & 1) ? UB1 : UB0);

        // mma: warp tile 64j x 64h, 2 E passes sharing B frags
        float acc[32][4];
        #pragma unroll
        for (int a = 0; a < 32; a++)
            #pragma unroll
            for (int c = 0; c < 4; c++) acc[a][c] = 0.f;

        #pragma unroll
        for (int ks = 0; ks < 4; ks++) {
            const int k0 = ks * 16;
            // B frags: 4 x ldmatrix.x4.trans covering k0..k0+15 x 64h
            u32 bfr[8][2];
            const int  kr  = k0 + lrow;
            const u32  brb = Ub + (u32)(kr * 128);
            const int  br7 = kr & 7;
            #pragma unroll
            for (int nb = 0; nb < 4; nb++) {
                const u32 addr = brb + (u32)((((nb*2 + lch) ^ br7)) << 4);
                ldsm4t(bfr[nb*2][0], bfr[nb*2][1],
                       bfr[nb*2+1][0], bfr[nb*2+1][1], addr);
            }
            #pragma unroll
            for (int jf = 0; jf < 4; jf++) {
                const int ra = wj + jf*16 + lrow;
                const u32 co = (u32)((((ks*2 + lch) ^ (ra & 7))) << 4);
                u32 ah[4], al[4];
                ldsm4(ah[0], ah[1], ah[2], ah[3], EhA + (u32)(ra*128) + co);
                ldsm4(al[0], al[1], al[2], al[3], ElA + (u32)(ra*128) + co);
                #pragma unroll
                for (int ht = 0; ht < 8; ht++) {
                    mma16816(acc[jf*8 + ht], ah, bfr[ht]);
                    mma16816(acc[jf*8 + ht], al, bfr[ht]);
                }
            }
        }

        // epilogue: relu + wd dot, bfly-reduce over lane%4, sigmoid, store
        {
            float ccr[16];
            const int t2 = (lane & 3) * 2;
            #pragma unroll
            for (int ht = 0; ht < 8; ht++) {
                ccr[ht*2]     = ccs[ii*64 + ht*8 + t2];
                ccr[ht*2 + 1] = ccs[ii*64 + ht*8 + t2 + 1];
            }
            const int ig2 = ibase + ii;
            #pragma unroll
            for (int jf = 0; jf < 4; jf++) {
                float s0 = 0.f, s1 = 0.f;
                #pragma unroll
                for (int ht = 0; ht < 8; ht++) {
                    s0 += fmaxf(acc[jf*8+ht][0] + ccr[ht*2],     0.f) * wdr[ht*2]
                        + fmaxf(acc[jf*8+ht][1] + ccr[ht*2 + 1], 0.f) * wdr[ht*2 + 1];
                    s1 += fmaxf(acc[jf*8+ht][2] + ccr[ht*2],     0.f) * wdr[ht*2]
                        + fmaxf(acc[jf*8+ht][3] + ccr[ht*2 + 1], 0.f) * wdr[ht*2 + 1];
                }
                s0 += __shfl_xor_sync(0xffffffffu, s0, 1);
                s0 += __shfl_xor_sync(0xffffffffu, s0, 2);
                s1 += __shfl_xor_sync(0xffffffffu, s1, 1);
                s1 += __shfl_xor_sync(0xffffffffu, s1, 2);
                if ((lane & 3) == 0) {
                    const int j0 = wj + jf*16 + (lane >> 2);
                    store_edge(out, b, ig2, j0,     s0 + bd);
                    store_edge(out, b, ig2, j0 + 8, s1 + bd);
                }
            }
        }
        __syncthreads();
    }
}

// =====================================================================
extern "C" void kernel_launch(void* const* d_in, const int* in_sizes, int n_in,
                              void* d_out, int out_size)
{
    (void)in_sizes; (void)n_in; (void)out_size;
    const float* nf   = (const float*)d_in[0];
    const float* fc1w = (const float*)d_in[1];
    const float* fc1b = (const float*)d_in[2];
    const float* fc2w = (const float*)d_in[3];
    const float* fc2b = (const float*)d_in[4];
    const float* e1w  = (const float*)d_in[5];
    const float* e1b  = (const float*)d_in[6];
    const float* e2w  = (const float*)d_in[7];
    const float* e2b  = (const float*)d_in[8];
    float* out = (float*)d_out;

    const int smem1 = 15424 * 4;
    cudaFuncSetAttribute(stage1, cudaFuncAttributeMaxDynamicSharedMemorySize, smem1);
    cudaFuncSetAttribute(stage2m, cudaFuncAttributeMaxDynamicSharedMemorySize, SM2_TOTAL);

    stage1<<<128, 256, smem1>>>(nf, fc1w, fc1b, fc2w, fc2b, e1w, out);
    stage2m<<<128, 256, SM2_TOTAL>>>(e1w, e1b, e2w, e2b, out);
}

// round 7
// speedup vs baseline: 1.5808x; 1.1065x over previous
#include <cuda_runtime.h>
#include <cuda_fp16.h>

// ---------------- problem constants ----------------
#define BSZ   4
#define NN    512
#define EMBD  64
#define INF   256          // IN_DIM
#define H1    128          // fc1 out (2*HD)
#define HE    64           // e1 out
#define NPAIR (NN*(NN-1))                 // 261632
#define PRED_OFF (BSZ*NN*NN)              // 1048576
#define EMB_OFF  (PRED_OFF + BSZ*NPAIR*2) // 3141632

// ---------------- device scratch (no allocs allowed) ----------------
__device__ float g_emb[BSZ*NN*EMBD];     // emb row-major [b][n][k]
__device__ float g_A  [BSZ*NN*HE];       // emb @ W1top   [b][n][h]

typedef unsigned int u32;

// =====================================================================
// Stage 1: node MLP (unchanged).
// =====================================================================
__global__ __launch_bounds__(256)
void stage1(const float* __restrict__ nf,
            const float* __restrict__ fc1w, const float* __restrict__ fc1b,
            const float* __restrict__ fc2w, const float* __restrict__ fc2b,
            const float* __restrict__ e1w,
            float* __restrict__ out)
{
    extern __shared__ float sm[];
    float* Xs = sm;             // 16*256 = 4096 floats
    float* Ws = Xs + 4096;      // up to 8192 floats
    float* Hs = Ws + 8192;      // 16*132 = 2112
    float* Es = Hs + 2112;      // 16*64  = 1024

    const int t  = threadIdx.x;
    const int nb = blockIdx.x * 16;
    const int node = t >> 4;
    const int sub  = t & 15;

    #pragma unroll
    for (int r = 0; r < 16; r++)
        Xs[t + r*256] = nf[nb*INF + t + r*256];

    {   // phase A: h = leaky(x@fc1+b1)
        const int hb = sub * 8;
        float acc[8];
        #pragma unroll
        for (int h = 0; h < 8; h++) acc[h] = 0.f;
        for (int kt = 0; kt < 4; kt++) {
            __syncthreads();
            #pragma unroll
            for (int r = 0; r < 32; r++)
                Ws[t + r*256] = fc1w[kt*64*H1 + t + r*256];
            __syncthreads();
            #pragma unroll
            for (int k = 0; k < 64; k++) {
                float x = Xs[node*INF + kt*64 + k];
                float4 w0 = *reinterpret_cast<const float4*>(&Ws[k*H1 + hb]);
                float4 w1 = *reinterpret_cast<const float4*>(&Ws[k*H1 + hb + 4]);
                acc[0] += x*w0.x; acc[1] += x*w0.y; acc[2] += x*w0.z; acc[3] += x*w0.w;
                acc[4] += x*w1.x; acc[5] += x*w1.y; acc[6] += x*w1.z; acc[7] += x*w1.w;
            }
        }
        #pragma unroll
        for (int h = 0; h < 8; h++) {
            float v = acc[h] + fc1b[hb + h];
            v = v > 0.f ? v : 0.01f * v;
            Hs[node*132 + hb + h] = v;
        }
    }

    __syncthreads();
    #pragma unroll
    for (int r = 0; r < 32; r++)
        Ws[t + r*256] = fc2w[t + r*256];
    __syncthreads();
    {   // phase B: emb = leaky(h@fc2+b2)
        const int db = sub * 4;
        float a0=0.f,a1=0.f,a2=0.f,a3=0.f;
        #pragma unroll
        for (int k = 0; k < H1; k++) {
            float hv = Hs[node*132 + k];
            float4 w = *reinterpret_cast<const float4*>(&Ws[k*EMBD + db]);
            a0 += hv*w.x; a1 += hv*w.y; a2 += hv*w.z; a3 += hv*w.w;
        }
        float v0 = a0 + fc2b[db+0]; v0 = v0 > 0.f ? v0 : 0.01f*v0;
        float v1 = a1 + fc2b[db+1]; v1 = v1 > 0.f ? v1 : 0.01f*v1;
        float v2 = a2 + fc2b[db+2]; v2 = v2 > 0.f ? v2 : 0.01f*v2;
        float v3 = a3 + fc2b[db+3]; v3 = v3 > 0.f ? v3 : 0.01f*v3;

        Es[node*EMBD + db + 0] = v0;
        Es[node*EMBD + db + 1] = v1;
        Es[node*EMBD + db + 2] = v2;
        Es[node*EMBD + db + 3] = v3;

        const int g = nb + node;
        float4 v4 = make_float4(v0, v1, v2, v3);
        *reinterpret_cast<float4*>(&g_emb[g*EMBD + db]) = v4;
        *reinterpret_cast<float4*>(&out[EMB_OFF + g*EMBD + db]) = v4;
    }

    __syncthreads();
    #pragma unroll
    for (int r = 0; r < 16; r++)
        Ws[t + r*256] = e1w[t + r*256];
    __syncthreads();
    {   // phase C: A = emb @ e1_w[:64,:]
        const int hb = sub * 4;
        float a0=0.f,a1=0.f,a2=0.f,a3=0.f;
        #pragma unroll
        for (int k = 0; k < EMBD; k++) {
            float ev = Es[node*EMBD + k];
            float4 w = *reinterpret_cast<const float4*>(&Ws[k*HE + hb]);
            a0 += ev*w.x; a1 += ev*w.y; a2 += ev*w.z; a3 += ev*w.w;
        }
        const int g = nb + node;
        *reinterpret_cast<float4*>(&g_A[g*HE + hb]) = make_float4(a0, a1, a2, a3);
    }
}

// =====================================================================
// Stage 2: edge GEMM via mma.sync fp16, E split (Eh+El), double-buffered U.
// Grid 128, 512 threads (16 warps), warp tile 32j x 64h, 1 CTA/SM.
// =====================================================================
// smem byte offsets
#define EHB   0          // Eh: 512 x 64 fp16, 128B rows, SW128   = 65536
#define ELB   65536      // El: same                               = 65536
#define UB0   131072     // U buf0: 64 x 64 fp16                   = 8192
#define UB1   139264     // U buf1                                 = 8192
#define WB    147456     // e1w fp32 (8192 floats)                 = 32768
#define EMBA  180224     // emb_i 16 x 64 f32                      = 4096
#define CCB   184320     // cc 16 x 64 f32                         = 4096
#define WDB   188416     // wd 64 f32                              = 256
#define SM2_TOTAL 188672

__device__ __forceinline__ u32 hpack(float lo, float hi) {
    __half2 h = __floats2half2_rn(lo, hi);
    return *reinterpret_cast<u32*>(&h);
}
__device__ __forceinline__ float h_lo(u32 p) {
    __half2 h = *reinterpret_cast<__half2*>(&p);
    return __low2float(h);
}
__device__ __forceinline__ float h_hi(u32 p) {
    __half2 h = *reinterpret_cast<__half2*>(&p);
    return __high2float(h);
}

__device__ __forceinline__ void ldsm4(u32& r0, u32& r1, u32& r2, u32& r3, u32 addr) {
    asm volatile("ldmatrix.sync.aligned.m8n8.x4.shared.b16 {%0,%1,%2,%3}, [%4];"
        : "=r"(r0), "=r"(r1), "=r"(r2), "=r"(r3) : "r"(addr));
}
__device__ __forceinline__ void ldsm4t(u32& r0, u32& r1, u32& r2, u32& r3, u32 addr) {
    asm volatile("ldmatrix.sync.aligned.m8n8.x4.trans.shared.b16 {%0,%1,%2,%3}, [%4];"
        : "=r"(r0), "=r"(r1), "=r"(r2), "=r"(r3) : "r"(addr));
}
__device__ __forceinline__ void mma16816(float* d, const u32* a, const u32* b) {
    asm volatile(
        "mma.sync.aligned.m16n8k16.row.col.f32.f16.f16.f32 "
        "{%0,%1,%2,%3}, {%4,%5,%6,%7}, {%8,%9}, {%0,%1,%2,%3};"
        : "+f"(d[0]), "+f"(d[1]), "+f"(d[2]), "+f"(d[3])
        : "r"(a[0]), "r"(a[1]), "r"(a[2]), "r"(a[3]), "r"(b[0]), "r"(b[1]));
}

__device__ __forceinline__ void store_edge(float* __restrict__ out,
                                           int b, int i, int j, float d) {
    float ad  = fabsf(d);
    float ex  = __expf(-ad);
    float inv = 1.f / (1.f + ex);
    float pbig = inv, psml = ex * inv;
    float p1 = d >= 0.f ? pbig : psml;
    float p0 = d >= 0.f ? psml : pbig;
    out[b*NN*NN + i*NN + j] = p1;
    if (j != i) {
        int kidx = i*(NN-1) + (j < i ? j : j - 1);
        reinterpret_cast<float2*>(out + PRED_OFF)[b*NPAIR + kidx] = make_float2(p0, p1);
    }
}

__global__ __launch_bounds__(512, 1)
void stage2m(const float* __restrict__ e1w, const float* __restrict__ e1b,
             const float* __restrict__ e2w, const float* __restrict__ e2b,
             float* __restrict__ out)
{
    extern __shared__ char smc[];
    const u32 sb = (u32)__cvta_generic_to_shared(smc);

    const int t    = threadIdx.x;
    const int lane = t & 31;
    const int wid  = t >> 5;          // 0..15
    const int b     = blockIdx.x >> 5;
    const int ibase = (blockIdx.x & 31) * 16;

    float* Wsm  = reinterpret_cast<float*>(smc + WB);
    float* embA = reinterpret_cast<float*>(smc + EMBA);
    float* ccs  = reinterpret_cast<float*>(smc + CCB);
    float* wds  = reinterpret_cast<float*>(smc + WDB);

    // ---- prologue: weights, emb_i, cc, wd ----
    #pragma unroll
    for (int r = 0; r < 4; r++)
        reinterpret_cast<float4*>(Wsm)[t + r*512] =
            reinterpret_cast<const float4*>(e1w)[t + r*512];
    if (t < 256)
        reinterpret_cast<float4*>(embA)[t] =
            reinterpret_cast<const float4*>(&g_emb[(b*NN + ibase)*EMBD])[t];
    #pragma unroll
    for (int r = 0; r < 2; r++) {
        int idx = t + r*512, ii = idx >> 6, h = idx & 63;
        ccs[idx] = g_A[(b*NN + ibase + ii)*HE + h] + e1b[h];
    }
    if (t < 64) wds[t] = e2w[t*2 + 1] - e2w[t*2];
    const float bd = e2b[1] - e2b[0];

    // ---- E conversion: row t (512 rows) -> Eh/El fp16 (SW128 swizzled) ----
    {
        const int r = t;
        const float4* src = reinterpret_cast<const float4*>(&g_emb[(b*NN + r)*EMBD]);
        char* ehrow = smc + EHB + r*128;
        char* elrow = smc + ELB + r*128;
        const int r7 = r & 7;
        #pragma unroll
        for (int c = 0; c < 8; c++) {
            float4 v0 = src[c*2], v1 = src[c*2 + 1];
            u32 h0 = hpack(v0.x, v0.y), h1 = hpack(v0.z, v0.w);
            u32 h2 = hpack(v1.x, v1.y), h3 = hpack(v1.z, v1.w);
            u32 l0 = hpack(v0.x - h_lo(h0), v0.y - h_hi(h0));
            u32 l1 = hpack(v0.z - h_lo(h1), v0.w - h_hi(h1));
            u32 l2 = hpack(v1.x - h_lo(h2), v1.y - h_hi(h2));
            u32 l3 = hpack(v1.z - h_lo(h3), v1.w - h_hi(h3));
            *reinterpret_cast<uint4*>(ehrow + ((c ^ r7) << 4)) = make_uint4(h0, h1, h2, h3);
            *reinterpret_cast<uint4*>(elrow + ((c ^ r7) << 4)) = make_uint4(l0, l1, l2, l3);
        }
    }
    __syncthreads();

    const u32 EhA = sb + EHB, ElA = sb + ELB;
    const int wj   = wid * 32;
    const int lrow = lane & 15;
    const int lch  = lane >> 4;      // 0/1: chunk selector

    // U build: 512 threads, thread -> (k = t>>3, chunk c = t&7 of 8 h)
    auto build_u = [&](int ii, u32 ubOff) {
        const int k = t >> 3;
        const int c = t & 7;
        const float e = embA[ii*64 + k];
        const float4* w1 = reinterpret_cast<const float4*>(&Wsm[k*64 + c*8]);
        const float4* w2 = reinterpret_cast<const float4*>(&Wsm[4096 + k*64 + c*8]);
        float4 a0 = w1[0], a1 = w1[1];
        float4 b0 = w2[0], b1 = w2[1];
        float u0 = fmaf(e, b0.x, -a0.x), u1 = fmaf(e, b0.y, -a0.y);
        float u2 = fmaf(e, b0.z, -a0.z), u3 = fmaf(e, b0.w, -a0.w);
        float u4 = fmaf(e, b1.x, -a1.x), u5 = fmaf(e, b1.y, -a1.y);
        float u6 = fmaf(e, b1.z, -a1.z), u7 = fmaf(e, b1.w, -a1.w);
        u32 p0 = hpack(u0, u1), p1 = hpack(u2, u3);
        u32 p2 = hpack(u4, u5), p3 = hpack(u6, u7);
        char* uh = smc + ubOff + k*128;
        *reinterpret_cast<uint4*>(uh + ((c ^ (k & 7)) << 4)) =
            make_uint4(p0, p1, p2, p3);
    };

    // build U[0], then sync so all warps see it
    build_u(0, UB0);
    __syncthreads();

    // ---- loop over 16 source nodes, U double-buffered ----
    for (int ii = 0; ii < 16; ii++) {
        if (ii + 1 < 16)
            build_u(ii + 1, ((ii + 1) & 1) ? UB1 : UB0);

        const u32 Ub = sb + ((ii & 1) ? UB1 : UB0);

        // mma: warp tile 32j x 64h, 2 E passes sharing B frags
        float acc[16][4];
        #pragma unroll
        for (int a = 0; a < 16; a++)
            #pragma unroll
            for (int c = 0; c < 4; c++) acc[a][c] = 0.f;

        #pragma unroll
        for (int ks = 0; ks < 4; ks++) {
            const int k0 = ks * 16;
            // B frags: 4 x ldmatrix.x4.trans covering k0..k0+15 x 64h
            u32 bfr[8][2];
            const int  kr  = k0 + lrow;
            const u32  brb = Ub + (u32)(kr * 128);
            const int  br7 = kr & 7;
            #pragma unroll
            for (int nb = 0; nb < 4; nb++) {
                const u32 addr = brb + (u32)((((nb*2 + lch) ^ br7)) << 4);
                ldsm4t(bfr[nb*2][0], bfr[nb*2][1],
                       bfr[nb*2+1][0], bfr[nb*2+1][1], addr);
            }
            #pragma unroll
            for (int jf = 0; jf < 2; jf++) {
                const int ra = wj + jf*16 + lrow;
                const u32 co = (u32)((((ks*2 + lch) ^ (ra & 7))) << 4);
                u32 ah[4], al[4];
                ldsm4(ah[0], ah[1], ah[2], ah[3], EhA + (u32)(ra*128) + co);
                ldsm4(al[0], al[1], al[2], al[3], ElA + (u32)(ra*128) + co);
                #pragma unroll
                for (int ht = 0; ht < 8; ht++) {
                    mma16816(acc[jf*8 + ht], ah, bfr[ht]);
                    mma16816(acc[jf*8 + ht], al, bfr[ht]);
                }
            }
        }

        // epilogue: relu + wd dot, bfly-reduce over lane%4, sigmoid, store
        {
            const int t2 = (lane & 3) * 2;
            const int ig2 = ibase + ii;
            #pragma unroll
            for (int jf = 0; jf < 2; jf++) {
                float s0 = 0.f, s1 = 0.f;
                #pragma unroll
                for (int ht = 0; ht < 8; ht++) {
                    float cc0 = ccs[ii*64 + ht*8 + t2];
                    float cc1 = ccs[ii*64 + ht*8 + t2 + 1];
                    float wd0 = wds[ht*8 + t2];
                    float wd1 = wds[ht*8 + t2 + 1];
                    s0 += fmaxf(acc[jf*8+ht][0] + cc0, 0.f) * wd0
                        + fmaxf(acc[jf*8+ht][1] + cc1, 0.f) * wd1;
                    s1 += fmaxf(acc[jf*8+ht][2] + cc0, 0.f) * wd0
                        + fmaxf(acc[jf*8+ht][3] + cc1, 0.f) * wd1;
                }
                s0 += __shfl_xor_sync(0xffffffffu, s0, 1);
                s0 += __shfl_xor_sync(0xffffffffu, s0, 2);
                s1 += __shfl_xor_sync(0xffffffffu, s1, 1);
                s1 += __shfl_xor_sync(0xffffffffu, s1, 2);
                if ((lane & 3) == 0) {
                    const int j0 = wj + jf*16 + (lane >> 2);
                    store_edge(out, b, ig2, j0,     s0 + bd);
                    store_edge(out, b, ig2, j0 + 8, s1 + bd);
                }
            }
        }
        __syncthreads();
    }
}

// =====================================================================
extern "C" void kernel_launch(void* const* d_in, const int* in_sizes, int n_in,
                              void* d_out, int out_size)
{
    (void)in_sizes; (void)n_in; (void)out_size;
    const float* nf   = (const float*)d_in[0];
    const float* fc1w = (const float*)d_in[1];
    const float* fc1b = (const float*)d_in[2];
    const float* fc2w = (const float*)d_in[3];
    const float* fc2b = (const float*)d_in[4];
    const float* e1w  = (const float*)d_in[5];
    const float* e1b  = (const float*)d_in[6];
    const float* e2w  = (const float*)d_in[7];
    const float* e2b  = (const float*)d_in[8];
    float* out = (float*)d_out;

    const int smem1 = 15424 * 4;
    cudaFuncSetAttribute(stage1, cudaFuncAttributeMaxDynamicSharedMemorySize, smem1);
    cudaFuncSetAttribute(stage2m, cudaFuncAttributeMaxDynamicSharedMemorySize, SM2_TOTAL);

    stage1<<<128, 256, smem1>>>(nf, fc1w, fc1b, fc2w, fc2b, e1w, out);
    stage2m<<<128, 512, SM2_TOTAL>>>(e1w, e1b, e2w, e2b, out);
}

// round 8
// speedup vs baseline: 1.8615x; 1.1775x over previous
#include <cuda_runtime.h>
#include <cuda_fp16.h>

// ---------------- problem constants ----------------
#define BSZ   4
#define NN    512
#define EMBD  64
#define INF   256          // IN_DIM
#define H1    128          // fc1 out (2*HD)
#define HE    64           // e1 out
#define NPAIR (NN*(NN-1))                 // 261632
#define PRED_OFF (BSZ*NN*NN)              // 1048576
#define EMB_OFF  (PRED_OFF + BSZ*NPAIR*2) // 3141632

// ---------------- device scratch (no allocs allowed) ----------------
__device__ float g_emb[BSZ*NN*EMBD];     // emb row-major [b][n][k]
__device__ float g_A  [BSZ*NN*HE];       // emb @ W1top   [b][n][h]

typedef unsigned int u32;

// =====================================================================
// Stage 1: node MLP (unchanged).
// =====================================================================
__global__ __launch_bounds__(256)
void stage1(const float* __restrict__ nf,
            const float* __restrict__ fc1w, const float* __restrict__ fc1b,
            const float* __restrict__ fc2w, const float* __restrict__ fc2b,
            const float* __restrict__ e1w,
            float* __restrict__ out)
{
    extern __shared__ float sm[];
    float* Xs = sm;             // 16*256 = 4096 floats
    float* Ws = Xs + 4096;      // up to 8192 floats
    float* Hs = Ws + 8192;      // 16*132 = 2112
    float* Es = Hs + 2112;      // 16*64  = 1024

    const int t  = threadIdx.x;
    const int nb = blockIdx.x * 16;
    const int node = t >> 4;
    const int sub  = t & 15;

    #pragma unroll
    for (int r = 0; r < 16; r++)
        Xs[t + r*256] = nf[nb*INF + t + r*256];

    {   // phase A: h = leaky(x@fc1+b1)
        const int hb = sub * 8;
        float acc[8];
        #pragma unroll
        for (int h = 0; h < 8; h++) acc[h] = 0.f;
        for (int kt = 0; kt < 4; kt++) {
            __syncthreads();
            #pragma unroll
            for (int r = 0; r < 32; r++)
                Ws[t + r*256] = fc1w[kt*64*H1 + t + r*256];
            __syncthreads();
            #pragma unroll
            for (int k = 0; k < 64; k++) {
                float x = Xs[node*INF + kt*64 + k];
                float4 w0 = *reinterpret_cast<const float4*>(&Ws[k*H1 + hb]);
                float4 w1 = *reinterpret_cast<const float4*>(&Ws[k*H1 + hb + 4]);
                acc[0] += x*w0.x; acc[1] += x*w0.y; acc[2] += x*w0.z; acc[3] += x*w0.w;
                acc[4] += x*w1.x; acc[5] += x*w1.y; acc[6] += x*w1.z; acc[7] += x*w1.w;
            }
        }
        #pragma unroll
        for (int h = 0; h < 8; h++) {
            float v = acc[h] + fc1b[hb + h];
            v = v > 0.f ? v : 0.01f * v;
            Hs[node*132 + hb + h] = v;
        }
    }

    __syncthreads();
    #pragma unroll
    for (int r = 0; r < 32; r++)
        Ws[t + r*256] = fc2w[t + r*256];
    __syncthreads();
    {   // phase B: emb = leaky(h@fc2+b2)
        const int db = sub * 4;
        float a0=0.f,a1=0.f,a2=0.f,a3=0.f;
        #pragma unroll
        for (int k = 0; k < H1; k++) {
            float hv = Hs[node*132 + k];
            float4 w = *reinterpret_cast<const float4*>(&Ws[k*EMBD + db]);
            a0 += hv*w.x; a1 += hv*w.y; a2 += hv*w.z; a3 += hv*w.w;
        }
        float v0 = a0 + fc2b[db+0]; v0 = v0 > 0.f ? v0 : 0.01f*v0;
        float v1 = a1 + fc2b[db+1]; v1 = v1 > 0.f ? v1 : 0.01f*v1;
        float v2 = a2 + fc2b[db+2]; v2 = v2 > 0.f ? v2 : 0.01f*v2;
        float v3 = a3 + fc2b[db+3]; v3 = v3 > 0.f ? v3 : 0.01f*v3;

        Es[node*EMBD + db + 0] = v0;
        Es[node*EMBD + db + 1] = v1;
        Es[node*EMBD + db + 2] = v2;
        Es[node*EMBD + db + 3] = v3;

        const int g = nb + node;
        float4 v4 = make_float4(v0, v1, v2, v3);
        *reinterpret_cast<float4*>(&g_emb[g*EMBD + db]) = v4;
        *reinterpret_cast<float4*>(&out[EMB_OFF + g*EMBD + db]) = v4;
    }

    __syncthreads();
    #pragma unroll
    for (int r = 0; r < 16; r++)
        Ws[t + r*256] = e1w[t + r*256];
    __syncthreads();
    {   // phase C: A = emb @ e1_w[:64,:]
        const int hb = sub * 4;
        float a0=0.f,a1=0.f,a2=0.f,a3=0.f;
        #pragma unroll
        for (int k = 0; k < EMBD; k++) {
            float ev = Es[node*EMBD + k];
            float4 w = *reinterpret_cast<const float4*>(&Ws[k*HE + hb]);
            a0 += ev*w.x; a1 += ev*w.y; a2 += ev*w.z; a3 += ev*w.w;
        }
        const int g = nb + node;
        *reinterpret_cast<float4*>(&g_A[g*HE + hb]) = make_float4(a0, a1, a2, a3);
    }
}

// =====================================================================
// Stage 2: edge GEMM via mma.sync fp16, SINGLE pass (E and U both fp16),
// double-buffered U. Grid 128, 512 threads, warp tile 32j x 64h.
// =====================================================================
// smem byte offsets
#define EHB   0          // Eh: 512 x 64 fp16, 128B rows, SW128   = 65536
#define UB0   65536      // U buf0: 64 x 64 fp16                   = 8192
#define UB1   73728      // U buf1                                 = 8192
#define WB    81920      // e1w fp32 (8192 floats)                 = 32768
#define EMBA  114688     // emb_i 16 x 64 f32                      = 4096
#define CCB   118784     // cc 16 x 64 f32                         = 4096
#define WDB   122880     // wd 64 f32                              = 256
#define SM2_TOTAL 123136

__device__ __forceinline__ u32 hpack(float lo, float hi) {
    __half2 h = __floats2half2_rn(lo, hi);
    return *reinterpret_cast<u32*>(&h);
}

__device__ __forceinline__ void ldsm4(u32& r0, u32& r1, u32& r2, u32& r3, u32 addr) {
    asm volatile("ldmatrix.sync.aligned.m8n8.x4.shared.b16 {%0,%1,%2,%3}, [%4];"
        : "=r"(r0), "=r"(r1), "=r"(r2), "=r"(r3) : "r"(addr));
}
__device__ __forceinline__ void ldsm4t(u32& r0, u32& r1, u32& r2, u32& r3, u32 addr) {
    asm volatile("ldmatrix.sync.aligned.m8n8.x4.trans.shared.b16 {%0,%1,%2,%3}, [%4];"
        : "=r"(r0), "=r"(r1), "=r"(r2), "=r"(r3) : "r"(addr));
}
__device__ __forceinline__ void mma16816(float* d, const u32* a, const u32* b) {
    asm volatile(
        "mma.sync.aligned.m16n8k16.row.col.f32.f16.f16.f32 "
        "{%0,%1,%2,%3}, {%4,%5,%6,%7}, {%8,%9}, {%0,%1,%2,%3};"
        : "+f"(d[0]), "+f"(d[1]), "+f"(d[2]), "+f"(d[3])
        : "r"(a[0]), "r"(a[1]), "r"(a[2]), "r"(a[3]), "r"(b[0]), "r"(b[1]));
}

__device__ __forceinline__ void store_edge(float* __restrict__ out,
                                           int b, int i, int j, float d) {
    float ad  = fabsf(d);
    float ex  = __expf(-ad);
    float inv = 1.f / (1.f + ex);
    float pbig = inv, psml = ex * inv;
    float p1 = d >= 0.f ? pbig : psml;
    float p0 = d >= 0.f ? psml : pbig;
    out[b*NN*NN + i*NN + j] = p1;
    if (j != i) {
        int kidx = i*(NN-1) + (j < i ? j : j - 1);
        reinterpret_cast<float2*>(out + PRED_OFF)[b*NPAIR + kidx] = make_float2(p0, p1);
    }
}

__global__ __launch_bounds__(512, 1)
void stage2m(const float* __restrict__ e1w, const float* __restrict__ e1b,
             const float* __restrict__ e2w, const float* __restrict__ e2b,
             float* __restrict__ out)
{
    extern __shared__ char smc[];
    const u32 sb = (u32)__cvta_generic_to_shared(smc);

    const int t    = threadIdx.x;
    const int lane = t & 31;
    const int wid  = t >> 5;          // 0..15
    const int b     = blockIdx.x >> 5;
    const int ibase = (blockIdx.x & 31) * 16;

    float* Wsm  = reinterpret_cast<float*>(smc + WB);
    float* embA = reinterpret_cast<float*>(smc + EMBA);
    float* ccs  = reinterpret_cast<float*>(smc + CCB);
    float* wds  = reinterpret_cast<float*>(smc + WDB);

    // ---- prologue: weights, emb_i, cc, wd ----
    #pragma unroll
    for (int r = 0; r < 4; r++)
        reinterpret_cast<float4*>(Wsm)[t + r*512] =
            reinterpret_cast<const float4*>(e1w)[t + r*512];
    if (t < 256)
        reinterpret_cast<float4*>(embA)[t] =
            reinterpret_cast<const float4*>(&g_emb[(b*NN + ibase)*EMBD])[t];
    #pragma unroll
    for (int r = 0; r < 2; r++) {
        int idx = t + r*512, ii = idx >> 6, h = idx & 63;
        ccs[idx] = g_A[(b*NN + ibase + ii)*HE + h] + e1b[h];
    }
    if (t < 64) wds[t] = e2w[t*2 + 1] - e2w[t*2];
    const float bd = e2b[1] - e2b[0];

    // ---- E conversion: row t (512 rows) -> Eh fp16 (SW128 swizzled) ----
    {
        const int r = t;
        const float4* src = reinterpret_cast<const float4*>(&g_emb[(b*NN + r)*EMBD]);
        char* ehrow = smc + EHB + r*128;
        const int r7 = r & 7;
        #pragma unroll
        for (int c = 0; c < 8; c++) {
            float4 v0 = src[c*2], v1 = src[c*2 + 1];
            u32 h0 = hpack(v0.x, v0.y), h1 = hpack(v0.z, v0.w);
            u32 h2 = hpack(v1.x, v1.y), h3 = hpack(v1.z, v1.w);
            *reinterpret_cast<uint4*>(ehrow + ((c ^ r7) << 4)) = make_uint4(h0, h1, h2, h3);
        }
    }
    __syncthreads();

    const u32 EhA = sb + EHB;
    const int wj   = wid * 32;
    const int lrow = lane & 15;
    const int lch  = lane >> 4;      // 0/1: chunk selector

    // U build: 512 threads, thread -> (k = t>>3, chunk c = t&7 of 8 h)
    auto build_u = [&](int ii, u32 ubOff) {
        const int k = t >> 3;
        const int c = t & 7;
        const float e = embA[ii*64 + k];
        const float4* w1 = reinterpret_cast<const float4*>(&Wsm[k*64 + c*8]);
        const float4* w2 = reinterpret_cast<const float4*>(&Wsm[4096 + k*64 + c*8]);
        float4 a0 = w1[0], a1 = w1[1];
        float4 b0 = w2[0], b1 = w2[1];
        float u0 = fmaf(e, b0.x, -a0.x), u1 = fmaf(e, b0.y, -a0.y);
        float u2 = fmaf(e, b0.z, -a0.z), u3 = fmaf(e, b0.w, -a0.w);
        float u4 = fmaf(e, b1.x, -a1.x), u5 = fmaf(e, b1.y, -a1.y);
        float u6 = fmaf(e, b1.z, -a1.z), u7 = fmaf(e, b1.w, -a1.w);
        u32 p0 = hpack(u0, u1), p1 = hpack(u2, u3);
        u32 p2 = hpack(u4, u5), p3 = hpack(u6, u7);
        char* uh = smc + ubOff + k*128;
        *reinterpret_cast<uint4*>(uh + ((c ^ (k & 7)) << 4)) =
            make_uint4(p0, p1, p2, p3);
    };

    // build U[0], then sync so all warps see it
    build_u(0, UB0);
    __syncthreads();

    // ---- loop over 16 source nodes, U double-buffered ----
    for (int ii = 0; ii < 16; ii++) {
        if (ii + 1 < 16)
            build_u(ii + 1, ((ii + 1) & 1) ? UB1 : UB0);

        const u32 Ub = sb + ((ii & 1) ? UB1 : UB0);

        // mma: warp tile 32j x 64h, single fp16 pass
        float acc[16][4];
        #pragma unroll
        for (int a = 0; a < 16; a++)
            #pragma unroll
            for (int c = 0; c < 4; c++) acc[a][c] = 0.f;

        #pragma unroll
        for (int ks = 0; ks < 4; ks++) {
            const int k0 = ks * 16;
            // B frags: 4 x ldmatrix.x4.trans covering k0..k0+15 x 64h
            u32 bfr[8][2];
            const int  kr  = k0 + lrow;
            const u32  brb = Ub + (u32)(kr * 128);
            const int  br7 = kr & 7;
            #pragma unroll
            for (int nb = 0; nb < 4; nb++) {
                const u32 addr = brb + (u32)((((nb*2 + lch) ^ br7)) << 4);
                ldsm4t(bfr[nb*2][0], bfr[nb*2][1],
                       bfr[nb*2+1][0], bfr[nb*2+1][1], addr);
            }
            #pragma unroll
            for (int jf = 0; jf < 2; jf++) {
                const int ra = wj + jf*16 + lrow;
                const u32 co = (u32)((((ks*2 + lch) ^ (ra & 7))) << 4);
                u32 ah[4];
                ldsm4(ah[0], ah[1], ah[2], ah[3], EhA + (u32)(ra*128) + co);
                #pragma unroll
                for (int ht = 0; ht < 8; ht++)
                    mma16816(acc[jf*8 + ht], ah, bfr[ht]);
            }
        }

        // epilogue: relu + wd dot, bfly-reduce over lane%4, sigmoid, store
        {
            const int t2 = (lane & 3) * 2;
            const int ig2 = ibase + ii;
            #pragma unroll
            for (int jf = 0; jf < 2; jf++) {
                float s0 = 0.f, s1 = 0.f;
                #pragma unroll
                for (int ht = 0; ht < 8; ht++) {
                    float cc0 = ccs[ii*64 + ht*8 + t2];
                    float cc1 = ccs[ii*64 + ht*8 + t2 + 1];
                    float wd0 = wds[ht*8 + t2];
                    float wd1 = wds[ht*8 + t2 + 1];
                    s0 += fmaxf(acc[jf*8+ht][0] + cc0, 0.f) * wd0
                        + fmaxf(acc[jf*8+ht][1] + cc1, 0.f) * wd1;
                    s1 += fmaxf(acc[jf*8+ht][2] + cc0, 0.f) * wd0
                        + fmaxf(acc[jf*8+ht][3] + cc1, 0.f) * wd1;
                }
                s0 += __shfl_xor_sync(0xffffffffu, s0, 1);
                s0 += __shfl_xor_sync(0xffffffffu, s0, 2);
                s1 += __shfl_xor_sync(0xffffffffu, s1, 1);
                s1 += __shfl_xor_sync(0xffffffffu, s1, 2);
                if ((lane & 3) == 0) {
                    const int j0 = wj + jf*16 + (lane >> 2);
                    store_edge(out, b, ig2, j0,     s0 + bd);
                    store_edge(out, b, ig2, j0 + 8, s1 + bd);
                }
            }
        }
        __syncthreads();
    }
}

// =====================================================================
extern "C" void kernel_launch(void* const* d_in, const int* in_sizes, int n_in,
                              void* d_out, int out_size)
{
    (void)in_sizes; (void)n_in; (void)out_size;
    const float* nf   = (const float*)d_in[0];
    const float* fc1w = (const float*)d_in[1];
    const float* fc1b = (const float*)d_in[2];
    const float* fc2w = (const float*)d_in[3];
    const float* fc2b = (const float*)d_in[4];
    const float* e1w  = (const float*)d_in[5];
    const float* e1b  = (const float*)d_in[6];
    const float* e2w  = (const float*)d_in[7];
    const float* e2b  = (const float*)d_in[8];
    float* out = (float*)d_out;

    const int smem1 = 15424 * 4;
    cudaFuncSetAttribute(stage1, cudaFuncAttributeMaxDynamicSharedMemorySize, smem1);
    cudaFuncSetAttribute(stage2m, cudaFuncAttributeMaxDynamicSharedMemorySize, SM2_TOTAL);

    stage1<<<128, 256, smem1>>>(nf, fc1w, fc1b, fc2w, fc2b, e1w, out);
    stage2m<<<128, 512, SM2_TOTAL>>>(e1w, e1b, e2w, e2b, out);
}

// round 9
// speedup vs baseline: 2.0847x; 1.1199x over previous
#include <cuda_runtime.h>
#include <cuda_fp16.h>

// ---------------- problem constants ----------------
#define BSZ   4
#define NN    512
#define EMBD  64
#define INF   256          // IN_DIM
#define H1    128          // fc1 out (2*HD)
#define HE    64           // e1 out
#define NPAIR (NN*(NN-1))                 // 261632
#define PRED_OFF (BSZ*NN*NN)              // 1048576
#define EMB_OFF  (PRED_OFF + BSZ*NPAIR*2) // 3141632

// ---------------- device scratch (no allocs allowed) ----------------
__device__ float g_emb[BSZ*NN*EMBD];     // emb row-major [b][n][k]
__device__ float g_A  [BSZ*NN*HE];       // emb @ W1top   [b][n][h]

typedef unsigned int u32;

// =====================================================================
// Stage 1: node MLP. 256 blocks x 256 threads, 8 nodes/block (32 thr/node).
// =====================================================================
__global__ __launch_bounds__(256)
void stage1(const float* __restrict__ nf,
            const float* __restrict__ fc1w, const float* __restrict__ fc1b,
            const float* __restrict__ fc2w, const float* __restrict__ fc2b,
            const float* __restrict__ e1w,
            float* __restrict__ out)
{
    extern __shared__ float sm[];
    float* Xs = sm;             // 8*256 = 2048 floats
    float* Ws = Xs + 2048;      // up to 8192 floats
    float* Hs = Ws + 8192;      // 8*132 = 1056
    float* Es = Hs + 1056;      // 8*64  = 512

    const int t  = threadIdx.x;
    const int nb = blockIdx.x * 8;
    const int node = t >> 5;                 // 0..7
    const int sub  = t & 31;                 // 0..31

    #pragma unroll
    for (int r = 0; r < 8; r++)
        Xs[t + r*256] = nf[nb*INF + t + r*256];

    {   // phase A: h = leaky(x@fc1+b1), 4 h-outputs per thread
        const int hb = sub * 4;
        float a0=0.f, a1=0.f, a2=0.f, a3=0.f;
        for (int kt = 0; kt < 4; kt++) {
            __syncthreads();
            #pragma unroll
            for (int r = 0; r < 32; r++)
                Ws[t + r*256] = fc1w[kt*64*H1 + t + r*256];
            __syncthreads();
            #pragma unroll
            for (int k = 0; k < 64; k++) {
                float x = Xs[node*INF + kt*64 + k];
                float4 w = *reinterpret_cast<const float4*>(&Ws[k*H1 + hb]);
                a0 += x*w.x; a1 += x*w.y; a2 += x*w.z; a3 += x*w.w;
            }
        }
        float v0 = a0 + fc1b[hb+0]; v0 = v0 > 0.f ? v0 : 0.01f*v0;
        float v1 = a1 + fc1b[hb+1]; v1 = v1 > 0.f ? v1 : 0.01f*v1;
        float v2 = a2 + fc1b[hb+2]; v2 = v2 > 0.f ? v2 : 0.01f*v2;
        float v3 = a3 + fc1b[hb+3]; v3 = v3 > 0.f ? v3 : 0.01f*v3;
        Hs[node*132 + hb + 0] = v0;
        Hs[node*132 + hb + 1] = v1;
        Hs[node*132 + hb + 2] = v2;
        Hs[node*132 + hb + 3] = v3;
    }

    __syncthreads();
    #pragma unroll
    for (int r = 0; r < 32; r++)       // fc2w: 8192 floats
        Ws[t + r*256] = fc2w[t + r*256];
    __syncthreads();
    {   // phase B: emb = leaky(h@fc2+b2), 2 outputs per thread
        const int db = sub * 2;
        float a0=0.f, a1=0.f;
        #pragma unroll
        for (int k = 0; k < H1; k++) {
            float hv = Hs[node*132 + k];
            float2 w = *reinterpret_cast<const float2*>(&Ws[k*EMBD + db]);
            a0 += hv*w.x; a1 += hv*w.y;
        }
        float v0 = a0 + fc2b[db+0]; v0 = v0 > 0.f ? v0 : 0.01f*v0;
        float v1 = a1 + fc2b[db+1]; v1 = v1 > 0.f ? v1 : 0.01f*v1;

        Es[node*EMBD + db + 0] = v0;
        Es[node*EMBD + db + 1] = v1;

        const int g = nb + node;
        float2 v2 = make_float2(v0, v1);
        *reinterpret_cast<float2*>(&g_emb[g*EMBD + db]) = v2;
        *reinterpret_cast<float2*>(&out[EMB_OFF + g*EMBD + db]) = v2;
    }

    __syncthreads();
    #pragma unroll
    for (int r = 0; r < 16; r++)       // e1w top half: 4096 floats
        Ws[t + r*256] = e1w[t + r*256];
    __syncthreads();
    {   // phase C: A = emb @ e1_w[:64,:], 2 outputs per thread
        const int hb = sub * 2;
        float a0=0.f, a1=0.f;
        #pragma unroll
        for (int k = 0; k < EMBD; k++) {
            float ev = Es[node*EMBD + k];
            float2 w = *reinterpret_cast<const float2*>(&Ws[k*HE + hb]);
            a0 += ev*w.x; a1 += ev*w.y;
        }
        const int g = nb + node;
        *reinterpret_cast<float2*>(&g_A[g*HE + hb]) = make_float2(a0, a1);
    }
}

// =====================================================================
// Stage 2: edge GEMM via mma.sync fp16 single pass. E A-frags cached in
// registers across the i-loop. Grid 128, 512 threads, warp tile 32j x 64h.
// =====================================================================
// smem byte offsets
#define EHB   0          // Eh: 512 x 64 fp16, 128B rows, SW128   = 65536
#define UB0   65536      // U buf0: 64 x 64 fp16                   = 8192
#define UB1   73728      // U buf1                                 = 8192
#define WB    81920      // e1w fp32 (8192 floats)                 = 32768
#define EMBA  114688     // emb_i 16 x 64 f32                      = 4096
#define CCB   118784     // cc 16 x 64 f32                         = 4096
#define WDB   122880     // wd 64 f32                              = 256
#define SM2_TOTAL 123136

__device__ __forceinline__ u32 hpack(float lo, float hi) {
    __half2 h = __floats2half2_rn(lo, hi);
    return *reinterpret_cast<u32*>(&h);
}

__device__ __forceinline__ void ldsm4(u32& r0, u32& r1, u32& r2, u32& r3, u32 addr) {
    asm volatile("ldmatrix.sync.aligned.m8n8.x4.shared.b16 {%0,%1,%2,%3}, [%4];"
        : "=r"(r0), "=r"(r1), "=r"(r2), "=r"(r3) : "r"(addr));
}
__device__ __forceinline__ void ldsm4t(u32& r0, u32& r1, u32& r2, u32& r3, u32 addr) {
    asm volatile("ldmatrix.sync.aligned.m8n8.x4.trans.shared.b16 {%0,%1,%2,%3}, [%4];"
        : "=r"(r0), "=r"(r1), "=r"(r2), "=r"(r3) : "r"(addr));
}
__device__ __forceinline__ void mma16816(float* d, const u32* a, const u32* b) {
    asm volatile(
        "mma.sync.aligned.m16n8k16.row.col.f32.f16.f16.f32 "
        "{%0,%1,%2,%3}, {%4,%5,%6,%7}, {%8,%9}, {%0,%1,%2,%3};"
        : "+f"(d[0]), "+f"(d[1]), "+f"(d[2]), "+f"(d[3])
        : "r"(a[0]), "r"(a[1]), "r"(a[2]), "r"(a[3]), "r"(b[0]), "r"(b[1]));
}

__device__ __forceinline__ void store_edge(float* __restrict__ out,
                                           int b, int i, int j, float d) {
    float ad  = fabsf(d);
    float ex  = __expf(-ad);
    float inv = 1.f / (1.f + ex);
    float pbig = inv, psml = ex * inv;
    float p1 = d >= 0.f ? pbig : psml;
    float p0 = d >= 0.f ? psml : pbig;
    out[b*NN*NN + i*NN + j] = p1;
    if (j != i) {
        int kidx = i*(NN-1) + (j < i ? j : j - 1);
        reinterpret_cast<float2*>(out + PRED_OFF)[b*NPAIR + kidx] = make_float2(p0, p1);
    }
}

__global__ __launch_bounds__(512, 1)
void stage2m(const float* __restrict__ e1w, const float* __restrict__ e1b,
             const float* __restrict__ e2w, const float* __restrict__ e2b,
             float* __restrict__ out)
{
    extern __shared__ char smc[];
    const u32 sb = (u32)__cvta_generic_to_shared(smc);

    const int t    = threadIdx.x;
    const int lane = t & 31;
    const int wid  = t >> 5;          // 0..15
    const int b     = blockIdx.x >> 5;
    const int ibase = (blockIdx.x & 31) * 16;

    float* Wsm  = reinterpret_cast<float*>(smc + WB);
    float* embA = reinterpret_cast<float*>(smc + EMBA);
    float* ccs  = reinterpret_cast<float*>(smc + CCB);
    float* wds  = reinterpret_cast<float*>(smc + WDB);

    // ---- prologue: weights, emb_i, cc, wd ----
    #pragma unroll
    for (int r = 0; r < 4; r++)
        reinterpret_cast<float4*>(Wsm)[t + r*512] =
            reinterpret_cast<const float4*>(e1w)[t + r*512];
    if (t < 256)
        reinterpret_cast<float4*>(embA)[t] =
            reinterpret_cast<const float4*>(&g_emb[(b*NN + ibase)*EMBD])[t];
    #pragma unroll
    for (int r = 0; r < 2; r++) {
        int idx = t + r*512, ii = idx >> 6, h = idx & 63;
        ccs[idx] = g_A[(b*NN + ibase + ii)*HE + h] + e1b[h];
    }
    if (t < 64) wds[t] = e2w[t*2 + 1] - e2w[t*2];
    const float bd = e2b[1] - e2b[0];

    // ---- E conversion: row t (512 rows) -> Eh fp16 (SW128 swizzled) ----
    {
        const int r = t;
        const float4* src = reinterpret_cast<const float4*>(&g_emb[(b*NN + r)*EMBD]);
        char* ehrow = smc + EHB + r*128;
        const int r7 = r & 7;
        #pragma unroll
        for (int c = 0; c < 8; c++) {
            float4 v0 = src[c*2], v1 = src[c*2 + 1];
            u32 h0 = hpack(v0.x, v0.y), h1 = hpack(v0.z, v0.w);
            u32 h2 = hpack(v1.x, v1.y), h3 = hpack(v1.z, v1.w);
            *reinterpret_cast<uint4*>(ehrow + ((c ^ r7) << 4)) = make_uint4(h0, h1, h2, h3);
        }
    }
    __syncthreads();

    const u32 EhA = sb + EHB;
    const int wj   = wid * 32;
    const int lrow = lane & 15;
    const int lch  = lane >> 4;      // 0/1: chunk selector

    // ---- preload E A-fragments for this warp: 32j x 64k = 8 x ldsm4 ----
    u32 ef[32];
    #pragma unroll
    for (int ks = 0; ks < 4; ks++) {
        #pragma unroll
        for (int jf = 0; jf < 2; jf++) {
            const int ra = wj + jf*16 + lrow;
            const u32 addr = EhA + (u32)(ra*128)
                           + (u32)((((ks*2 + lch) ^ (ra & 7))) << 4);
            u32* e = &ef[(ks*2 + jf)*4];
            ldsm4(e[0], e[1], e[2], e[3], addr);
        }
    }

    // U build: 512 threads, thread -> (k = t>>3, chunk c = t&7 of 8 h)
    auto build_u = [&](int ii, u32 ubOff) {
        const int k = t >> 3;
        const int c = t & 7;
        const float e = embA[ii*64 + k];
        const float4* w1 = reinterpret_cast<const float4*>(&Wsm[k*64 + c*8]);
        const float4* w2 = reinterpret_cast<const float4*>(&Wsm[4096 + k*64 + c*8]);
        float4 a0 = w1[0], a1 = w1[1];
        float4 b0 = w2[0], b1 = w2[1];
        float u0 = fmaf(e, b0.x, -a0.x), u1 = fmaf(e, b0.y, -a0.y);
        float u2 = fmaf(e, b0.z, -a0.z), u3 = fmaf(e, b0.w, -a0.w);
        float u4 = fmaf(e, b1.x, -a1.x), u5 = fmaf(e, b1.y, -a1.y);
        float u6 = fmaf(e, b1.z, -a1.z), u7 = fmaf(e, b1.w, -a1.w);
        u32 p0 = hpack(u0, u1), p1 = hpack(u2, u3);
        u32 p2 = hpack(u4, u5), p3 = hpack(u6, u7);
        char* uh = smc + ubOff + k*128;
        *reinterpret_cast<uint4*>(uh + ((c ^ (k & 7)) << 4)) =
            make_uint4(p0, p1, p2, p3);
    };

    // build U[0], then sync so all warps see it
    build_u(0, UB0);
    __syncthreads();

    // ---- loop over 16 source nodes, U double-buffered ----
    for (int ii = 0; ii < 16; ii++) {
        if (ii + 1 < 16)
            build_u(ii + 1, ((ii + 1) & 1) ? UB1 : UB0);

        const u32 Ub = sb + ((ii & 1) ? UB1 : UB0);

        // mma: warp tile 32j x 64h; B-frags in h-halves (8 regs live)
        float acc[16][4];
        #pragma unroll
        for (int a = 0; a < 16; a++)
            #pragma unroll
            for (int c = 0; c < 4; c++) acc[a][c] = 0.f;

        #pragma unroll
        for (int ks = 0; ks < 4; ks++) {
            const int  kr  = ks*16 + lrow;
            const u32  brb = Ub + (u32)(kr * 128);
            const int  br7 = kr & 7;
            #pragma unroll
            for (int hh = 0; hh < 2; hh++) {
                // 2 x ldsm4t -> 4 B-frags covering 16k x 32h
                u32 bfr[4][2];
                #pragma unroll
                for (int nb = 0; nb < 2; nb++) {
                    const u32 addr = brb +
                        (u32)(((((hh*2 + nb)*2 + lch) ^ br7)) << 4);
                    ldsm4t(bfr[nb*2][0], bfr[nb*2][1],
                           bfr[nb*2+1][0], bfr[nb*2+1][1], addr);
                }
                #pragma unroll
                for (int jf = 0; jf < 2; jf++) {
                    const u32* a = &ef[(ks*2 + jf)*4];
                    #pragma unroll
                    for (int h4 = 0; h4 < 4; h4++)
                        mma16816(acc[jf*8 + hh*4 + h4], a, bfr[h4]);
                }
            }
        }

        // epilogue: relu + wd dot, bfly-reduce over lane%4, sigmoid, store
        {
            const int t2 = (lane & 3) * 2;
            const int ig2 = ibase + ii;
            #pragma unroll
            for (int jf = 0; jf < 2; jf++) {
                float s0 = 0.f, s1 = 0.f;
                #pragma unroll
                for (int ht = 0; ht < 8; ht++) {
                    float cc0 = ccs[ii*64 + ht*8 + t2];
                    float cc1 = ccs[ii*64 + ht*8 + t2 + 1];
                    float wd0 = wds[ht*8 + t2];
                    float wd1 = wds[ht*8 + t2 + 1];
                    s0 += fmaxf(acc[jf*8+ht][0] + cc0, 0.f) * wd0
                        + fmaxf(acc[jf*8+ht][1] + cc1, 0.f) * wd1;
                    s1 += fmaxf(acc[jf*8+ht][2] + cc0, 0.f) * wd0
                        + fmaxf(acc[jf*8+ht][3] + cc1, 0.f) * wd1;
                }
                s0 += __shfl_xor_sync(0xffffffffu, s0, 1);
                s0 += __shfl_xor_sync(0xffffffffu, s0, 2);
                s1 += __shfl_xor_sync(0xffffffffu, s1, 1);
                s1 += __shfl_xor_sync(0xffffffffu, s1, 2);
                if ((lane & 3) == 0) {
                    const int j0 = wj + jf*16 + (lane >> 2);
                    store_edge(out, b, ig2, j0,     s0 + bd);
                    store_edge(out, b, ig2, j0 + 8, s1 + bd);
                }
            }
        }
        __syncthreads();
    }
}

// =====================================================================
extern "C" void kernel_launch(void* const* d_in, const int* in_sizes, int n_in,
                              void* d_out, int out_size)
{
    (void)in_sizes; (void)n_in; (void)out_size;
    const float* nf   = (const float*)d_in[0];
    const float* fc1w = (const float*)d_in[1];
    const float* fc1b = (const float*)d_in[2];
    const float* fc2w = (const float*)d_in[3];
    const float* fc2b = (const float*)d_in[4];
    const float* e1w  = (const float*)d_in[5];
    const float* e1b  = (const float*)d_in[6];
    const float* e2w  = (const float*)d_in[7];
    const float* e2b  = (const float*)d_in[8];
    float* out = (float*)d_out;

    const int smem1 = 11800 * 4;   // 47200 B
    cudaFuncSetAttribute(stage1, cudaFuncAttributeMaxDynamicSharedMemorySize, smem1);
    cudaFuncSetAttribute(stage2m, cudaFuncAttributeMaxDynamicSharedMemorySize, SM2_TOTAL);

    stage1<<<256, 256, smem1>>>(nf, fc1w, fc1b, fc2w, fc2b, e1w, out);
    stage2m<<<128, 512, SM2_TOTAL>>>(e1w, e1b, e2w, e2b, out);
}

// round 10
// speedup vs baseline: 2.2666x; 1.0873x over previous
#include <cuda_runtime.h>
#include <cuda_fp16.h>

// ---------------- problem constants ----------------
#define BSZ   4
#define NN    512
#define EMBD  64
#define INF   256          // IN_DIM
#define H1    128          // fc1 out (2*HD)
#define HE    64           // e1 out
#define NPAIR (NN*(NN-1))                 // 261632
#define PRED_OFF (BSZ*NN*NN)              // 1048576
#define EMB_OFF  (PRED_OFF + BSZ*NPAIR*2) // 3141632

// ---------------- device scratch (no allocs allowed) ----------------
__device__ float g_emb[BSZ*NN*EMBD];     // emb row-major [b][n][k]
__device__ float g_A  [BSZ*NN*HE];       // emb @ W1top   [b][n][h]

typedef unsigned int u32;

// =====================================================================
// Stage 1: node MLP. 256 blocks x 256 threads, 8 nodes/block.
// =====================================================================
__global__ __launch_bounds__(256)
void stage1(const float* __restrict__ nf,
            const float* __restrict__ fc1w, const float* __restrict__ fc1b,
            const float* __restrict__ fc2w, const float* __restrict__ fc2b,
            const float* __restrict__ e1w,
            float* __restrict__ out)
{
    extern __shared__ float sm[];
    float* Xs = sm;             // 8*256 = 2048 floats
    float* Ws = Xs + 2048;      // up to 8192 floats
    float* Hs = Ws + 8192;      // 8*132 = 1056
    float* Es = Hs + 1056;      // 8*64  = 512

    const int t  = threadIdx.x;
    const int nb = blockIdx.x * 8;
    const int node = t >> 5;                 // 0..7
    const int sub  = t & 31;                 // 0..31

    #pragma unroll
    for (int r = 0; r < 8; r++)
        Xs[t + r*256] = nf[nb*INF + t + r*256];

    {   // phase A: h = leaky(x@fc1+b1), 4 h-outputs per thread
        const int hb = sub * 4;
        float a0=0.f, a1=0.f, a2=0.f, a3=0.f;
        for (int kt = 0; kt < 4; kt++) {
            __syncthreads();
            #pragma unroll
            for (int r = 0; r < 32; r++)
                Ws[t + r*256] = fc1w[kt*64*H1 + t + r*256];
            __syncthreads();
            #pragma unroll
            for (int k = 0; k < 64; k++) {
                float x = Xs[node*INF + kt*64 + k];
                float4 w = *reinterpret_cast<const float4*>(&Ws[k*H1 + hb]);
                a0 += x*w.x; a1 += x*w.y; a2 += x*w.z; a3 += x*w.w;
            }
        }
        float v0 = a0 + fc1b[hb+0]; v0 = v0 > 0.f ? v0 : 0.01f*v0;
        float v1 = a1 + fc1b[hb+1]; v1 = v1 > 0.f ? v1 : 0.01f*v1;
        float v2 = a2 + fc1b[hb+2]; v2 = v2 > 0.f ? v2 : 0.01f*v2;
        float v3 = a3 + fc1b[hb+3]; v3 = v3 > 0.f ? v3 : 0.01f*v3;
        Hs[node*132 + hb + 0] = v0;
        Hs[node*132 + hb + 1] = v1;
        Hs[node*132 + hb + 2] = v2;
        Hs[node*132 + hb + 3] = v3;
    }

    __syncthreads();
    #pragma unroll
    for (int r = 0; r < 32; r++)       // fc2w: 8192 floats
        Ws[t + r*256] = fc2w[t + r*256];
    __syncthreads();
    {   // phase B: emb = leaky(h@fc2+b2), 2 outputs per thread
        const int db = sub * 2;
        float a0=0.f, a1=0.f;
        #pragma unroll
        for (int k = 0; k < H1; k++) {
            float hv = Hs[node*132 + k];
            float2 w = *reinterpret_cast<const float2*>(&Ws[k*EMBD + db]);
            a0 += hv*w.x; a1 += hv*w.y;
        }
        float v0 = a0 + fc2b[db+0]; v0 = v0 > 0.f ? v0 : 0.01f*v0;
        float v1 = a1 + fc2b[db+1]; v1 = v1 > 0.f ? v1 : 0.01f*v1;

        Es[node*EMBD + db + 0] = v0;
        Es[node*EMBD + db + 1] = v1;

        const int g = nb + node;
        float2 v2 = make_float2(v0, v1);
        *reinterpret_cast<float2*>(&g_emb[g*EMBD + db]) = v2;
        *reinterpret_cast<float2*>(&out[EMB_OFF + g*EMBD + db]) = v2;
    }

    __syncthreads();
    #pragma unroll
    for (int r = 0; r < 16; r++)       // e1w top half: 4096 floats
        Ws[t + r*256] = e1w[t + r*256];
    __syncthreads();
    {   // phase C: A = emb @ e1_w[:64,:], 2 outputs per thread
        const int hb = sub * 2;
        float a0=0.f, a1=0.f;
        #pragma unroll
        for (int k = 0; k < EMBD; k++) {
            float ev = Es[node*EMBD + k];
            float2 w = *reinterpret_cast<const float2*>(&Ws[k*HE + hb]);
            a0 += ev*w.x; a1 += ev*w.y;
        }
        const int g = nb + node;
        *reinterpret_cast<float2*>(&g_A[g*HE + hb]) = make_float2(a0, a1);
    }
}

// =====================================================================
// Stage 2: edge GEMM via mma.sync fp16 single pass. U built 8-at-a-time,
// barrier-free processing phases. Grid 128, 512 threads, 32j x 64h/warp.
// =====================================================================
// smem byte offsets
#define EHB   0          // Eh: 512 x 64 fp16, 128B rows, SW128   = 65536
#define UB    65536      // U bufs: 8 x (64 x 64 fp16 = 8192)      = 65536
#define WB    131072     // e1w fp32 (8192 floats)                 = 32768
#define EMBA  163840     // emb_i 16 x 64 f32                      = 4096
#define CCB   167936     // cc 16 x 64 f32                         = 4096
#define WDB   172032     // wd 64 f32                              = 256
#define SM2_TOTAL 172288

__device__ __forceinline__ u32 hpack(float lo, float hi) {
    __half2 h = __floats2half2_rn(lo, hi);
    return *reinterpret_cast<u32*>(&h);
}

__device__ __forceinline__ void ldsm4(u32& r0, u32& r1, u32& r2, u32& r3, u32 addr) {
    asm volatile("ldmatrix.sync.aligned.m8n8.x4.shared.b16 {%0,%1,%2,%3}, [%4];"
        : "=r"(r0), "=r"(r1), "=r"(r2), "=r"(r3) : "r"(addr));
}
__device__ __forceinline__ void ldsm4t(u32& r0, u32& r1, u32& r2, u32& r3, u32 addr) {
    asm volatile("ldmatrix.sync.aligned.m8n8.x4.trans.shared.b16 {%0,%1,%2,%3}, [%4];"
        : "=r"(r0), "=r"(r1), "=r"(r2), "=r"(r3) : "r"(addr));
}
__device__ __forceinline__ void mma16816(float* d, const u32* a, const u32* b) {
    asm volatile(
        "mma.sync.aligned.m16n8k16.row.col.f32.f16.f16.f32 "
        "{%0,%1,%2,%3}, {%4,%5,%6,%7}, {%8,%9}, {%0,%1,%2,%3};"
        : "+f"(d[0]), "+f"(d[1]), "+f"(d[2]), "+f"(d[3])
        : "r"(a[0]), "r"(a[1]), "r"(a[2]), "r"(a[3]), "r"(b[0]), "r"(b[1]));
}

__device__ __forceinline__ void store_edge(float* __restrict__ out,
                                           int b, int i, int j, float d) {
    float ad  = fabsf(d);
    float ex  = __expf(-ad);
    float inv = 1.f / (1.f + ex);
    float pbig = inv, psml = ex * inv;
    float p1 = d >= 0.f ? pbig : psml;
    float p0 = d >= 0.f ? psml : pbig;
    out[b*NN*NN + i*NN + j] = p1;
    if (j != i) {
        int kidx = i*(NN-1) + (j < i ? j : j - 1);
        reinterpret_cast<float2*>(out + PRED_OFF)[b*NPAIR + kidx] = make_float2(p0, p1);
    }
}

__global__ __launch_bounds__(512, 1)
void stage2m(const float* __restrict__ e1w, const float* __restrict__ e1b,
             const float* __restrict__ e2w, const float* __restrict__ e2b,
             float* __restrict__ out)
{
    extern __shared__ char smc[];
    const u32 sb = (u32)__cvta_generic_to_shared(smc);

    const int t    = threadIdx.x;
    const int lane = t & 31;
    const int wid  = t >> 5;          // 0..15
    const int b     = blockIdx.x >> 5;
    const int ibase = (blockIdx.x & 31) * 16;

    float* Wsm  = reinterpret_cast<float*>(smc + WB);
    float* embA = reinterpret_cast<float*>(smc + EMBA);
    float* ccs  = reinterpret_cast<float*>(smc + CCB);
    float* wds  = reinterpret_cast<float*>(smc + WDB);

    // ---- prologue: weights, emb_i, cc, wd ----
    #pragma unroll
    for (int r = 0; r < 4; r++)
        reinterpret_cast<float4*>(Wsm)[t + r*512] =
            reinterpret_cast<const float4*>(e1w)[t + r*512];
    if (t < 256)
        reinterpret_cast<float4*>(embA)[t] =
            reinterpret_cast<const float4*>(&g_emb[(b*NN + ibase)*EMBD])[t];
    #pragma unroll
    for (int r = 0; r < 2; r++) {
        int idx = t + r*512, ii = idx >> 6, h = idx & 63;
        ccs[idx] = g_A[(b*NN + ibase + ii)*HE + h] + e1b[h];
    }
    if (t < 64) wds[t] = e2w[t*2 + 1] - e2w[t*2];
    const float bd = e2b[1] - e2b[0];

    // ---- E conversion: row t (512 rows) -> Eh fp16 (SW128 swizzled) ----
    {
        const int r = t;
        const float4* src = reinterpret_cast<const float4*>(&g_emb[(b*NN + r)*EMBD]);
        char* ehrow = smc + EHB + r*128;
        const int r7 = r & 7;
        #pragma unroll
        for (int c = 0; c < 8; c++) {
            float4 v0 = src[c*2], v1 = src[c*2 + 1];
            u32 h0 = hpack(v0.x, v0.y), h1 = hpack(v0.z, v0.w);
            u32 h2 = hpack(v1.x, v1.y), h3 = hpack(v1.z, v1.w);
            *reinterpret_cast<uint4*>(ehrow + ((c ^ r7) << 4)) = make_uint4(h0, h1, h2, h3);
        }
    }
    __syncthreads();

    const u32 EhA = sb + EHB;
    const int wj   = wid * 32;
    const int lrow = lane & 15;
    const int lch  = lane >> 4;      // 0/1: chunk selector

    // ---- preload E A-fragments for this warp: 32j x 64k = 8 x ldsm4 ----
    u32 ef[32];
    #pragma unroll
    for (int ks = 0; ks < 4; ks++) {
        #pragma unroll
        for (int jf = 0; jf < 2; jf++) {
            const int ra = wj + jf*16 + lrow;
            const u32 addr = EhA + (u32)(ra*128)
                           + (u32)((((ks*2 + lch) ^ (ra & 7))) << 4);
            u32* e = &ef[(ks*2 + jf)*4];
            ldsm4(e[0], e[1], e[2], e[3], addr);
        }
    }

    // U batch build: thread -> (k = t>>3, chunk c = t&7 of 8 h), 8 i's/phase
    auto build_u8 = [&](int phase) {
        const int k = t >> 3;
        const int c = t & 7;
        const float4* w1 = reinterpret_cast<const float4*>(&Wsm[k*64 + c*8]);
        const float4* w2 = reinterpret_cast<const float4*>(&Wsm[4096 + k*64 + c*8]);
        float4 a0 = w1[0], a1 = w1[1];
        float4 b0 = w2[0], b1 = w2[1];
        const u32 co = (u32)((c ^ (k & 7)) << 4);
        #pragma unroll
        for (int q = 0; q < 8; q++) {
            const float e = embA[(phase*8 + q)*64 + k];
            float u0 = fmaf(e, b0.x, -a0.x), u1 = fmaf(e, b0.y, -a0.y);
            float u2 = fmaf(e, b0.z, -a0.z), u3 = fmaf(e, b0.w, -a0.w);
            float u4 = fmaf(e, b1.x, -a1.x), u5 = fmaf(e, b1.y, -a1.y);
            float u6 = fmaf(e, b1.z, -a1.z), u7 = fmaf(e, b1.w, -a1.w);
            u32 p0 = hpack(u0, u1), p1 = hpack(u2, u3);
            u32 p2 = hpack(u4, u5), p3 = hpack(u6, u7);
            char* uh = smc + UB + q*8192 + k*128;
            *reinterpret_cast<uint4*>(uh + co) = make_uint4(p0, p1, p2, p3);
        }
    };

    // ---- two phases of (build 8 U's, barrier, process 8 i's barrier-free) ----
    for (int phase = 0; phase < 2; phase++) {
        build_u8(phase);
        __syncthreads();

        #pragma unroll
        for (int q = 0; q < 8; q++) {
            const int ii = phase*8 + q;
            const u32 Ub = sb + UB + (u32)(q*8192);

            float acc[16][4];
            #pragma unroll
            for (int a = 0; a < 16; a++)
                #pragma unroll
                for (int c = 0; c < 4; c++) acc[a][c] = 0.f;

            #pragma unroll
            for (int ks = 0; ks < 4; ks++) {
                const int  kr  = ks*16 + lrow;
                const u32  brb = Ub + (u32)(kr * 128);
                const int  br7 = kr & 7;
                #pragma unroll
                for (int hh = 0; hh < 2; hh++) {
                    u32 bfr[4][2];
                    #pragma unroll
                    for (int nb = 0; nb < 2; nb++) {
                        const u32 addr = brb +
                            (u32)(((((hh*2 + nb)*2 + lch) ^ br7)) << 4);
                        ldsm4t(bfr[nb*2][0], bfr[nb*2][1],
                               bfr[nb*2+1][0], bfr[nb*2+1][1], addr);
                    }
                    #pragma unroll
                    for (int jf = 0; jf < 2; jf++) {
                        const u32* a = &ef[(ks*2 + jf)*4];
                        #pragma unroll
                        for (int h4 = 0; h4 < 4; h4++)
                            mma16816(acc[jf*8 + hh*4 + h4], a, bfr[h4]);
                    }
                }
            }

            // epilogue: relu + wd dot, bfly-reduce over lane%4, sigmoid, store
            const int t2 = (lane & 3) * 2;
            const int ig2 = ibase + ii;
            #pragma unroll
            for (int jf = 0; jf < 2; jf++) {
                float s0 = 0.f, s1 = 0.f;
                #pragma unroll
                for (int ht = 0; ht < 8; ht++) {
                    float cc0 = ccs[ii*64 + ht*8 + t2];
                    float cc1 = ccs[ii*64 + ht*8 + t2 + 1];
                    float wd0 = wds[ht*8 + t2];
                    float wd1 = wds[ht*8 + t2 + 1];
                    s0 += fmaxf(acc[jf*8+ht][0] + cc0, 0.f) * wd0
                        + fmaxf(acc[jf*8+ht][1] + cc1, 0.f) * wd1;
                    s1 += fmaxf(acc[jf*8+ht][2] + cc0, 0.f) * wd0
                        + fmaxf(acc[jf*8+ht][3] + cc1, 0.f) * wd1;
                }
                s0 += __shfl_xor_sync(0xffffffffu, s0, 1);
                s0 += __shfl_xor_sync(0xffffffffu, s0, 2);
                s1 += __shfl_xor_sync(0xffffffffu, s1, 1);
                s1 += __shfl_xor_sync(0xffffffffu, s1, 2);
                if ((lane & 3) == 0) {
                    const int j0 = wj + jf*16 + (lane >> 2);
                    store_edge(out, b, ig2, j0,     s0 + bd);
                    store_edge(out, b, ig2, j0 + 8, s1 + bd);
                }
            }
        }
        if (phase == 0) __syncthreads();   // all reads of U bufs done before rebuild
    }
}

// =====================================================================
extern "C" void kernel_launch(void* const* d_in, const int* in_sizes, int n_in,
                              void* d_out, int out_size)
{
    (void)in_sizes; (void)n_in; (void)out_size;
    const float* nf   = (const float*)d_in[0];
    const float* fc1w = (const float*)d_in[1];
    const float* fc1b = (const float*)d_in[2];
    const float* fc2w = (const float*)d_in[3];
    const float* fc2b = (const float*)d_in[4];
    const float* e1w  = (const float*)d_in[5];
    const float* e1b  = (const float*)d_in[6];
    const float* e2w  = (const float*)d_in[7];
    const float* e2b  = (const float*)d_in[8];
    float* out = (float*)d_out;

    const int smem1 = 11800 * 4;   // 47200 B
    cudaFuncSetAttribute(stage1, cudaFuncAttributeMaxDynamicSharedMemorySize, smem1);
    cudaFuncSetAttribute(stage2m, cudaFuncAttributeMaxDynamicSharedMemorySize, SM2_TOTAL);

    stage1<<<256, 256, smem1>>>(nf, fc1w, fc1b, fc2w, fc2b, e1w, out);
    stage2m<<<128, 512, SM2_TOTAL>>>(e1w, e1b, e2w, e2b, out);
}

// round 11
// speedup vs baseline: 2.4992x; 1.1026x over previous
#include <cuda_runtime.h>
#include <cuda_fp16.h>

// ---------------- problem constants ----------------
#define BSZ   4
#define NN    512
#define EMBD  64
#define INF   256          // IN_DIM
#define H1    128          // fc1 out (2*HD)
#define HE    64           // e1 out
#define NPAIR (NN*(NN-1))                 // 261632
#define PRED_OFF (BSZ*NN*NN)              // 1048576
#define EMB_OFF  (PRED_OFF + BSZ*NPAIR*2) // 3141632

// ---------------- device scratch (no allocs allowed) ----------------
__device__ float g_emb[BSZ*NN*EMBD];     // emb row-major [b][n][k]
__device__ float g_A  [BSZ*NN*HE];       // emb @ W1top   [b][n][h]

typedef unsigned int u32;

// =====================================================================
// Stage 1: node MLP. 256 blocks x 256 threads, 8 nodes/block.
// Double-buffered weight staging (reg prefetch -> STS), 6 barriers total.
// =====================================================================
__global__ __launch_bounds__(256)
void stage1(const float* __restrict__ nf,
            const float* __restrict__ fc1w, const float* __restrict__ fc1b,
            const float* __restrict__ fc2w, const float* __restrict__ fc2b,
            const float* __restrict__ e1w,
            float* __restrict__ out)
{
    extern __shared__ float sm[];
    float* Xs  = sm;            // 8*256 = 2048 floats
    float* Ws0 = Xs + 2048;     // 8192 floats
    float* Ws1 = Ws0 + 8192;    // 8192 floats
    float* Hs  = Ws1 + 8192;    // 8*132 = 1056
    float* Es  = Hs + 1056;     // 8*64  = 512
    // total 20000 floats = 80000 B

    const int t  = threadIdx.x;
    const int nb = blockIdx.x * 8;
    const int node = t >> 5;                 // 0..7
    const int sub  = t & 31;                 // 0..31

    #pragma unroll
    for (int r = 0; r < 8; r++)
        Xs[t + r*256] = nf[nb*INF + t + r*256];

    const float4* fw1 = reinterpret_cast<const float4*>(fc1w);
    const float4* fw2 = reinterpret_cast<const float4*>(fc2w);
    const float4* ew  = reinterpret_cast<const float4*>(e1w);

    // prefetch fc1w tile 0
    float4 pf[8];
    #pragma unroll
    for (int r = 0; r < 8; r++) pf[r] = fw1[t + r*256];

    float a0=0.f, a1=0.f, a2=0.f, a3=0.f;
    const int hb = sub * 4;

    #pragma unroll
    for (int kt = 0; kt < 4; kt++) {
        float* W = (kt & 1) ? Ws1 : Ws0;
        #pragma unroll
        for (int r = 0; r < 8; r++)
            reinterpret_cast<float4*>(W)[t + r*256] = pf[r];
        __syncthreads();
        // prefetch next tile (fc1w kt+1, or fc2w after the last)
        if (kt < 3) {
            #pragma unroll
            for (int r = 0; r < 8; r++) pf[r] = fw1[(kt+1)*2048 + t + r*256];
        } else {
            #pragma unroll
            for (int r = 0; r < 8; r++) pf[r] = fw2[t + r*256];
        }
        #pragma unroll
        for (int k = 0; k < 64; k++) {
            float x = Xs[node*INF + kt*64 + k];
            float4 w = *reinterpret_cast<const float4*>(&W[k*H1 + hb]);
            a0 += x*w.x; a1 += x*w.y; a2 += x*w.z; a3 += x*w.w;
        }
    }
    {
        float v0 = a0 + fc1b[hb+0]; v0 = v0 > 0.f ? v0 : 0.01f*v0;
        float v1 = a1 + fc1b[hb+1]; v1 = v1 > 0.f ? v1 : 0.01f*v1;
        float v2 = a2 + fc1b[hb+2]; v2 = v2 > 0.f ? v2 : 0.01f*v2;
        float v3 = a3 + fc1b[hb+3]; v3 = v3 > 0.f ? v3 : 0.01f*v3;
        Hs[node*132 + hb + 0] = v0;
        Hs[node*132 + hb + 1] = v1;
        Hs[node*132 + hb + 2] = v2;
        Hs[node*132 + hb + 3] = v3;
    }

    // ---- phase B: stage fc2w (already prefetched) into Ws0 ----
    #pragma unroll
    for (int r = 0; r < 8; r++)
        reinterpret_cast<float4*>(Ws0)[t + r*256] = pf[r];
    __syncthreads();
    // prefetch e1w top half (4096 floats = 1024 float4)
    float4 pe[4];
    #pragma unroll
    for (int r = 0; r < 4; r++) pe[r] = ew[t + r*256];
    {
        const int db = sub * 2;
        float b0=0.f, b1=0.f;
        #pragma unroll
        for (int k = 0; k < H1; k++) {
            float hv = Hs[node*132 + k];
            float2 w = *reinterpret_cast<const float2*>(&Ws0[k*EMBD + db]);
            b0 += hv*w.x; b1 += hv*w.y;
        }
        float v0 = b0 + fc2b[db+0]; v0 = v0 > 0.f ? v0 : 0.01f*v0;
        float v1 = b1 + fc2b[db+1]; v1 = v1 > 0.f ? v1 : 0.01f*v1;

        Es[node*EMBD + db + 0] = v0;
        Es[node*EMBD + db + 1] = v1;

        const int g = nb + node;
        float2 v2 = make_float2(v0, v1);
        *reinterpret_cast<float2*>(&g_emb[g*EMBD + db]) = v2;
        *reinterpret_cast<float2*>(&out[EMB_OFF + g*EMBD + db]) = v2;
    }

    // ---- phase C: stage e1w top into Ws1 ----
    #pragma unroll
    for (int r = 0; r < 4; r++)
        reinterpret_cast<float4*>(Ws1)[t + r*256] = pe[r];
    __syncthreads();
    {
        const int hb2 = sub * 2;
        float c0=0.f, c1=0.f;
        #pragma unroll
        for (int k = 0; k < EMBD; k++) {
            float ev = Es[node*EMBD + k];
            float2 w = *reinterpret_cast<const float2*>(&Ws1[k*HE + hb2]);
            c0 += ev*w.x; c1 += ev*w.y;
        }
        const int g = nb + node;
        *reinterpret_cast<float2*>(&g_A[g*HE + hb2]) = make_float2(c0, c1);
    }
}

// =====================================================================
// Stage 2: edge GEMM via mma.sync fp16 single pass. U built 8-at-a-time,
// barrier-free phases; zero-C first mma; hoisted B offsets; 32-lane epilogue.
// =====================================================================
// smem byte offsets
#define EHB   0          // Eh: 512 x 64 fp16, 128B rows, SW128   = 65536
#define UB    65536      // U bufs: 8 x (64 x 64 fp16 = 8192)      = 65536
#define WB    131072     // e1w fp32 (8192 floats)                 = 32768
#define EMBA  163840     // emb_i 16 x 64 f32                      = 4096
#define CCB   167936     // cc 16 x 64 f32                         = 4096
#define WDB   172032     // wd 64 f32                              = 256
#define SM2_TOTAL 172288

__device__ __forceinline__ u32 hpack(float lo, float hi) {
    __half2 h = __floats2half2_rn(lo, hi);
    return *reinterpret_cast<u32*>(&h);
}

__device__ __forceinline__ void ldsm4(u32& r0, u32& r1, u32& r2, u32& r3, u32 addr) {
    asm volatile("ldmatrix.sync.aligned.m8n8.x4.shared.b16 {%0,%1,%2,%3}, [%4];"
        : "=r"(r0), "=r"(r1), "=r"(r2), "=r"(r3) : "r"(addr));
}
__device__ __forceinline__ void ldsm4t(u32& r0, u32& r1, u32& r2, u32& r3, u32 addr) {
    asm volatile("ldmatrix.sync.aligned.m8n8.x4.trans.shared.b16 {%0,%1,%2,%3}, [%4];"
        : "=r"(r0), "=r"(r1), "=r"(r2), "=r"(r3) : "r"(addr));
}
__device__ __forceinline__ void mma16816(float* d, const u32* a, const u32* b) {
    asm volatile(
        "mma.sync.aligned.m16n8k16.row.col.f32.f16.f16.f32 "
        "{%0,%1,%2,%3}, {%4,%5,%6,%7}, {%8,%9}, {%0,%1,%2,%3};"
        : "+f"(d[0]), "+f"(d[1]), "+f"(d[2]), "+f"(d[3])
        : "r"(a[0]), "r"(a[1]), "r"(a[2]), "r"(a[3]), "r"(b[0]), "r"(b[1]));
}
// first k-step: C = 0 (no acc-init MOVs needed)
__device__ __forceinline__ void mma16816_z(float* d, const u32* a, const u32* b) {
    asm volatile(
        "mma.sync.aligned.m16n8k16.row.col.f32.f16.f16.f32 "
        "{%0,%1,%2,%3}, {%4,%5,%6,%7}, {%8,%9}, {%10,%10,%10,%10};"
        : "=f"(d[0]), "=f"(d[1]), "=f"(d[2]), "=f"(d[3])
        : "r"(a[0]), "r"(a[1]), "r"(a[2]), "r"(a[3]), "r"(b[0]), "r"(b[1]),
          "f"(0.f));
}

__device__ __forceinline__ void store_edge(float* __restrict__ out,
                                           int b, int i, int j, float d) {
    float ad  = fabsf(d);
    float ex  = __expf(-ad);
    float inv = 1.f / (1.f + ex);
    float pbig = inv, psml = ex * inv;
    float p1 = d >= 0.f ? pbig : psml;
    float p0 = d >= 0.f ? psml : pbig;
    out[b*NN*NN + i*NN + j] = p1;
    if (j != i) {
        int kidx = i*(NN-1) + (j < i ? j : j - 1);
        reinterpret_cast<float2*>(out + PRED_OFF)[b*NPAIR + kidx] = make_float2(p0, p1);
    }
}

__global__ __launch_bounds__(512, 1)
void stage2m(const float* __restrict__ e1w, const float* __restrict__ e1b,
             const float* __restrict__ e2w, const float* __restrict__ e2b,
             float* __restrict__ out)
{
    extern __shared__ char smc[];
    const u32 sb = (u32)__cvta_generic_to_shared(smc);

    const int t    = threadIdx.x;
    const int lane = t & 31;
    const int wid  = t >> 5;          // 0..15
    const int b     = blockIdx.x >> 5;
    const int ibase = (blockIdx.x & 31) * 16;

    float* Wsm  = reinterpret_cast<float*>(smc + WB);
    float* embA = reinterpret_cast<float*>(smc + EMBA);
    float* ccs  = reinterpret_cast<float*>(smc + CCB);
    float* wds  = reinterpret_cast<float*>(smc + WDB);

    // ---- prologue: weights, emb_i, cc, wd ----
    #pragma unroll
    for (int r = 0; r < 4; r++)
        reinterpret_cast<float4*>(Wsm)[t + r*512] =
            reinterpret_cast<const float4*>(e1w)[t + r*512];
    if (t < 256)
        reinterpret_cast<float4*>(embA)[t] =
            reinterpret_cast<const float4*>(&g_emb[(b*NN + ibase)*EMBD])[t];
    #pragma unroll
    for (int r = 0; r < 2; r++) {
        int idx = t + r*512, ii = idx >> 6, h = idx & 63;
        ccs[idx] = g_A[(b*NN + ibase + ii)*HE + h] + e1b[h];
    }
    if (t < 64) wds[t] = e2w[t*2 + 1] - e2w[t*2];
    const float bd = e2b[1] - e2b[0];

    // ---- E conversion: row t (512 rows) -> Eh fp16 (SW128 swizzled) ----
    {
        const int r = t;
        const float4* src = reinterpret_cast<const float4*>(&g_emb[(b*NN + r)*EMBD]);
        char* ehrow = smc + EHB + r*128;
        const int r7 = r & 7;
        #pragma unroll
        for (int c = 0; c < 8; c++) {
            float4 v0 = src[c*2], v1 = src[c*2 + 1];
            u32 h0 = hpack(v0.x, v0.y), h1 = hpack(v0.z, v0.w);
            u32 h2 = hpack(v1.x, v1.y), h3 = hpack(v1.z, v1.w);
            *reinterpret_cast<uint4*>(ehrow + ((c ^ r7) << 4)) = make_uint4(h0, h1, h2, h3);
        }
    }
    __syncthreads();

    const u32 EhA = sb + EHB;
    const int wj   = wid * 32;
    const int lrow = lane & 15;
    const int lch  = lane >> 4;      // 0/1: chunk selector

    // ---- preload E A-fragments for this warp: 32j x 64k = 8 x ldsm4 ----
    u32 ef[32];
    #pragma unroll
    for (int ks = 0; ks < 4; ks++) {
        #pragma unroll
        for (int jf = 0; jf < 2; jf++) {
            const int ra = wj + jf*16 + lrow;
            const u32 addr = EhA + (u32)(ra*128)
                           + (u32)((((ks*2 + lch) ^ (ra & 7))) << 4);
            u32* e = &ef[(ks*2 + jf)*4];
            ldsm4(e[0], e[1], e[2], e[3], addr);
        }
    }

    // ---- hoisted B-frag swizzled offsets (i-invariant): [ks][hh], nb=0 ----
    u32 boff[8];
    #pragma unroll
    for (int ks = 0; ks < 4; ks++) {
        #pragma unroll
        for (int hh = 0; hh < 2; hh++) {
            const int kr = ks*16 + lrow;
            boff[ks*2 + hh] = (u32)(kr*128 + (((hh*4 + lch) ^ (kr & 7)) << 4));
        }
    }

    // U batch build: thread -> (k = t>>3, chunk c = t&7 of 8 h), 8 i's/phase
    auto build_u8 = [&](int phase) {
        const int k = t >> 3;
        const int c = t & 7;
        const float4* w1 = reinterpret_cast<const float4*>(&Wsm[k*64 + c*8]);
        const float4* w2 = reinterpret_cast<const float4*>(&Wsm[4096 + k*64 + c*8]);
        float4 a0 = w1[0], a1 = w1[1];
        float4 b0 = w2[0], b1 = w2[1];
        const u32 co = (u32)((c ^ (k & 7)) << 4);
        #pragma unroll
        for (int q = 0; q < 8; q++) {
            const float e = embA[(phase*8 + q)*64 + k];
            float u0 = fmaf(e, b0.x, -a0.x), u1 = fmaf(e, b0.y, -a0.y);
            float u2 = fmaf(e, b0.z, -a0.z), u3 = fmaf(e, b0.w, -a0.w);
            float u4 = fmaf(e, b1.x, -a1.x), u5 = fmaf(e, b1.y, -a1.y);
            float u6 = fmaf(e, b1.z, -a1.z), u7 = fmaf(e, b1.w, -a1.w);
            u32 p0 = hpack(u0, u1), p1 = hpack(u2, u3);
            u32 p2 = hpack(u4, u5), p3 = hpack(u6, u7);
            char* uh = smc + UB + q*8192 + k*128;
            *reinterpret_cast<uint4*>(uh + co) = make_uint4(p0, p1, p2, p3);
        }
    };

    // ---- two phases of (build 8 U's, barrier, process 8 i's barrier-free) ----
    for (int phase = 0; phase < 2; phase++) {
        build_u8(phase);
        __syncthreads();

        #pragma unroll
        for (int q = 0; q < 8; q++) {
            const int ii = phase*8 + q;
            const u32 Ub = sb + UB + (u32)(q*8192);

            float acc[16][4];

            #pragma unroll
            for (int ks = 0; ks < 4; ks++) {
                #pragma unroll
                for (int hh = 0; hh < 2; hh++) {
                    const u32 a0addr = Ub + boff[ks*2 + hh];
                    u32 bfr[4][2];
                    ldsm4t(bfr[0][0], bfr[0][1], bfr[1][0], bfr[1][1], a0addr);
                    ldsm4t(bfr[2][0], bfr[2][1], bfr[3][0], bfr[3][1], a0addr ^ 32u);
                    #pragma unroll
                    for (int jf = 0; jf < 2; jf++) {
                        const u32* a = &ef[(ks*2 + jf)*4];
                        #pragma unroll
                        for (int h4 = 0; h4 < 4; h4++) {
                            if (ks == 0)
                                mma16816_z(acc[jf*8 + hh*4 + h4], a, bfr[h4]);
                            else
                                mma16816(acc[jf*8 + hh*4 + h4], a, bfr[h4]);
                        }
                    }
                }
            }

            // ---- epilogue: relu + wd dot, quad reduce, 32-lane distribute ----
            const int t2 = (lane & 3) * 2;
            const int ig2 = ibase + ii;
            float2 ccw[8], wdw[8];
            #pragma unroll
            for (int ht = 0; ht < 8; ht++) {
                ccw[ht] = *reinterpret_cast<const float2*>(&ccs[ii*64 + ht*8 + t2]);
                wdw[ht] = *reinterpret_cast<const float2*>(&wds[ht*8 + t2]);
            }
            float p[4];
            #pragma unroll
            for (int jf = 0; jf < 2; jf++) {
                float s0 = 0.f, s1 = 0.f;
                #pragma unroll
                for (int ht = 0; ht < 8; ht++) {
                    s0 += fmaxf(acc[jf*8+ht][0] + ccw[ht].x, 0.f) * wdw[ht].x
                        + fmaxf(acc[jf*8+ht][1] + ccw[ht].y, 0.f) * wdw[ht].y;
                    s1 += fmaxf(acc[jf*8+ht][2] + ccw[ht].x, 0.f) * wdw[ht].x
                        + fmaxf(acc[jf*8+ht][3] + ccw[ht].y, 0.f) * wdw[ht].y;
                }
                s0 += __shfl_xor_sync(0xffffffffu, s0, 1);
                s0 += __shfl_xor_sync(0xffffffffu, s0, 2);
                s1 += __shfl_xor_sync(0xffffffffu, s1, 1);
                s1 += __shfl_xor_sync(0xffffffffu, s1, 2);
                p[jf*2 + 0] = s0;
                p[jf*2 + 1] = s1;
            }
            // distribute: lane L handles q2 = L>>3 (jf = L>>4, s = (L>>3)&1),
            // g = L&7, value lives in quad g (source lane 4g).
            const int g   = lane & 7;
            const int src = g * 4;
            float v0 = __shfl_sync(0xffffffffu, p[0], src);
            float v1 = __shfl_sync(0xffffffffu, p[1], src);
            float v2 = __shfl_sync(0xffffffffu, p[2], src);
            float v3 = __shfl_sync(0xffffffffu, p[3], src);
            const int q2 = lane >> 3;
            float d = (q2 == 0) ? v0 : (q2 == 1) ? v1 : (q2 == 2) ? v2 : v3;
            d += bd;
            const int j = wj + ((lane >> 4) << 4) + (((lane >> 3) & 1) << 3) + g;
            store_edge(out, b, ig2, j, d);
        }
        if (phase == 0) __syncthreads();   // all reads of U bufs done before rebuild
    }
}

// =====================================================================
extern "C" void kernel_launch(void* const* d_in, const int* in_sizes, int n_in,
                              void* d_out, int out_size)
{
    (void)in_sizes; (void)n_in; (void)out_size;
    const float* nf   = (const float*)d_in[0];
    const float* fc1w = (const float*)d_in[1];
    const float* fc1b = (const float*)d_in[2];
    const float* fc2w = (const float*)d_in[3];
    const float* fc2b = (const float*)d_in[4];
    const float* e1w  = (const float*)d_in[5];
    const float* e1b  = (const float*)d_in[6];
    const float* e2w  = (const float*)d_in[7];
    const float* e2b  = (const float*)d_in[8];
    float* out = (float*)d_out;

    const int smem1 = 20000 * 4;   // 80000 B
    cudaFuncSetAttribute(stage1, cudaFuncAttributeMaxDynamicSharedMemorySize, smem1);
    cudaFuncSetAttribute(stage2m, cudaFuncAttributeMaxDynamicSharedMemorySize, SM2_TOTAL);

    stage1<<<256, 256, smem1>>>(nf, fc1w, fc1b, fc2w, fc2b, e1w, out);
    stage2m<<<128, 512, SM2_TOTAL>>>(e1w, e1b, e2w, e2b, out);
}